// round 3
// baseline (speedup 1.0000x reference)
#include <cuda_runtime.h>
#include <cstdint>

// SetAbstraction fused kernel, round 3: 512 threads (16 warps, RPW=4) for latency
// hiding; packed f32x2 FMA + cp.async double-buffered weight staging.
// One CTA = 2 query points (64 rows).

#define NT 512
#define MB 2
#define KNB 32
#define ROWS 64          // MB*KNB
#define RPW 4            // rows per warp (16 warps)
#define CT 32            // weight rows per staged chunk
#define LDX0 96          // padded stride of X0 (67 real cols -> 96)

typedef unsigned long long ull;

__device__ __forceinline__ ull pk2(float a, float b) {
    ull r; asm("mov.b64 %0,{%1,%2};" : "=l"(r) : "f"(a), "f"(b)); return r;
}
__device__ __forceinline__ void up2(ull v, float& a, float& b) {
    asm("mov.b64 {%0,%1},%2;" : "=f"(a), "=f"(b) : "l"(v));
}
__device__ __forceinline__ ull add2(ull a, ull b) {
    ull r; asm("add.rn.f32x2 %0,%1,%2;" : "=l"(r) : "l"(a), "l"(b)); return r;
}
__device__ __forceinline__ void fma2(ull& d, ull a, ull b) {
    asm("fma.rn.f32x2 %0,%1,%2,%0;" : "+l"(d) : "l"(a), "l"(b));
}
__device__ __forceinline__ ull fma2r(ull a, ull b, ull c) {
    ull r; asm("fma.rn.f32x2 %0,%1,%2,%3;" : "=l"(r) : "l"(a), "l"(b), "l"(c)); return r;
}

#define CP_COMMIT asm volatile("cp.async.commit_group;")
#define CP_WAIT0  asm volatile("cp.async.wait_group 0;")

__device__ __forceinline__ void cpa16(float* dst, const float* src) {
    unsigned d = (unsigned)__cvta_generic_to_shared(dst);
    asm volatile("cp.async.ca.shared.global [%0], [%1], 16;" :: "r"(d), "l"(src));
}

__device__ __forceinline__ float warp_sum(float v) {
#pragma unroll
    for (int o = 16; o > 0; o >>= 1) v += __shfl_xor_sync(0xffffffffu, v, o);
    return v;
}

// Stage CT rows x FO cols of W (rows >= FI zero-filled) into smem buf via cp.async.
template <int FO>
__device__ __forceinline__ void stage(float* buf, const float* __restrict__ W,
                                      int c0, int FI) {
    constexpr int VPR = FO / 4;       // 16B vectors per row
    constexpr int NV  = CT * VPR;
    const int tid = threadIdx.x;
#pragma unroll
    for (int i = tid; i < NV; i += NT) {
        int row = i / VPR;
        int gc  = c0 + row;
        if (gc < FI) cpa16(buf + i * 4, W + (size_t)gc * FO + (i % VPR) * 4);
        else         *reinterpret_cast<float4*>(buf + i * 4) = make_float4(0.f, 0.f, 0.f, 0.f);
    }
}

// acc[r][NB*2] packed col-pairs. Lane owns cols {blk*128 + lane*4 .. +3} per block.
template <int FO>
__device__ __forceinline__ void gemm_chunk(const float* Xs, int ldx, int c0,
                                           const float* Wc, ull (*acc)[FO / 64]) {
    constexpr int NB = FO / 128;
    const int lane = threadIdx.x & 31, warp = threadIdx.x >> 5;
    const int r0 = warp * RPW;
    const float* wbase = Wc + lane * 4;
#pragma unroll 4
    for (int c = 0; c < CT; c += 4) {
        float4 xv[RPW];
#pragma unroll
        for (int r = 0; r < RPW; r++)
            xv[r] = *reinterpret_cast<const float4*>(Xs + (r0 + r) * ldx + c0 + c);
#pragma unroll
        for (int cc = 0; cc < 4; cc++) {
            ull w[NB][2];
#pragma unroll
            for (int b = 0; b < NB; b++) {
                ulonglong2 wv = *reinterpret_cast<const ulonglong2*>(wbase + (c + cc) * FO + b * 128);
                w[b][0] = wv.x; w[b][1] = wv.y;
            }
#pragma unroll
            for (int r = 0; r < RPW; r++) {
                float x = (cc == 0) ? xv[r].x : (cc == 1) ? xv[r].y : (cc == 2) ? xv[r].z : xv[r].w;
                ull xd = pk2(x, x);
#pragma unroll
                for (int b = 0; b < NB; b++) {
                    fma2(acc[r][b * 2 + 0], xd, w[b][0]);
                    fma2(acc[r][b * 2 + 1], xd, w[b][1]);
                }
            }
        }
    }
}

// LayerNorm + ReLU epilogue; stores float4 (conflict-free).
template <int FO>
__device__ __forceinline__ void ln_epi(ull (*acc)[FO / 64],
                                       const float* __restrict__ b, const float* __restrict__ g,
                                       const float* __restrict__ be, float* Ys) {
    constexpr int NB = FO / 128;
    const int lane = threadIdx.x & 31, warp = threadIdx.x >> 5;
    const int r0 = warp * RPW;
    ull bp[NB][2], gp[NB][2], bep[NB][2];
#pragma unroll
    for (int bb = 0; bb < NB; bb++) {
        ulonglong2 t;
        t = *reinterpret_cast<const ulonglong2*>(b  + bb * 128 + lane * 4); bp[bb][0] = t.x; bp[bb][1] = t.y;
        t = *reinterpret_cast<const ulonglong2*>(g  + bb * 128 + lane * 4); gp[bb][0] = t.x; gp[bb][1] = t.y;
        t = *reinterpret_cast<const ulonglong2*>(be + bb * 128 + lane * 4); bep[bb][0] = t.x; bep[bb][1] = t.y;
    }
    const float invFO = 1.f / (float)FO;
#pragma unroll
    for (int r = 0; r < RPW; r++) {
        ull s = 0ull, q = 0ull;
#pragma unroll
        for (int bb = 0; bb < NB; bb++)
#pragma unroll
            for (int p = 0; p < 2; p++) {
                ull v = add2(acc[r][bb * 2 + p], bp[bb][p]);
                acc[r][bb * 2 + p] = v;
                s = add2(s, v);
                q = fma2r(v, v, q);
            }
        float sl, sh, ql, qh; up2(s, sl, sh); up2(q, ql, qh);
        ull sq = pk2(sl + sh, ql + qh);
#pragma unroll
        for (int o = 16; o > 0; o >>= 1) sq = add2(sq, __shfl_xor_sync(0xffffffffu, sq, o));
        float S, Q; up2(sq, S, Q);
        float mean = S * invFO;
        float var  = fmaxf(Q * invFO - mean * mean, 0.f);
        float inv  = rsqrtf(var + 1e-5f);
        ull vInv = pk2(inv, inv), vOff = pk2(-mean * inv, -mean * inv);
#pragma unroll
        for (int bb = 0; bb < NB; bb++) {
            ull t0 = fma2r(fma2r(acc[r][bb * 2 + 0], vInv, vOff), gp[bb][0], bep[bb][0]);
            ull t1 = fma2r(fma2r(acc[r][bb * 2 + 1], vInv, vOff), gp[bb][1], bep[bb][1]);
            float4 o;
            up2(t0, o.x, o.y); up2(t1, o.z, o.w);
            o.x = fmaxf(o.x, 0.f); o.y = fmaxf(o.y, 0.f);
            o.z = fmaxf(o.z, 0.f); o.w = fmaxf(o.w, 0.f);
            *reinterpret_cast<float4*>(Ys + (r0 + r) * FO + bb * 128 + lane * 4) = o;
        }
    }
}

extern __shared__ float smem[];

__global__ __launch_bounds__(NT, 1)
void sa_fused_kernel(const float* __restrict__ xyz, const float* __restrict__ feat,
                     const int* __restrict__ scanidx, const int* __restrict__ group_idx,
                     const float* __restrict__ W1, const float* __restrict__ b1,
                     const float* __restrict__ g1, const float* __restrict__ be1,
                     const float* __restrict__ W2, const float* __restrict__ b2,
                     const float* __restrict__ g2, const float* __restrict__ be2,
                     const float* __restrict__ W3, const float* __restrict__ b3,
                     const float* __restrict__ g3, const float* __restrict__ be3,
                     const float* __restrict__ Wa1, const float* __restrict__ ba1,
                     const float* __restrict__ Wa2, const float* __restrict__ ba2,
                     const float* __restrict__ Wo, const float* __restrict__ bo,
                     float* __restrict__ out_xyz, float* __restrict__ out_feat) {
    float* X0s    = smem;                        // 64*96
    float* H12s   = X0s + ROWS * LDX0;           // 64*128 (H1 then H2 in place)
    float* H3s    = H12s + ROWS * 128;           // 64*256
    float* Wc0    = H3s + ROWS * 256;            // 32*256
    float* Wc1    = Wc0 + CT * 256;              // 32*256
    float* scores = Wc1 + CT * 256;              // 64
    float* wgt    = scores + ROWS;               // 64
    float* wsum   = wgt + ROWS;                  // 2*256
    int*   gidx   = (int*)(wsum + MB * 256);     // 64

    float* WcB[2] = { Wc0, Wc1 };

    const int tid  = threadIdx.x;
    const int lane = tid & 31, warp = tid >> 5;
    const int r0   = warp * RPW;
    const int m0   = blockIdx.x * MB;

    // Prefetch L1 chunk 0 immediately (overlaps with gather).
    stage<128>(WcB[0], W1, 0, 67);
    CP_COMMIT;

    // ---- gather phase ----
    for (int i = tid; i < ROWS * LDX0; i += NT) X0s[i] = 0.f;
    if (tid < ROWS) gidx[tid] = group_idx[(size_t)(m0 + (tid >> 5)) * KNB + (tid & 31)];
    __syncthreads();
    if (tid < ROWS) {
        int g = gidx[tid];
        int s = scanidx[m0 + (tid >> 5)];
#pragma unroll
        for (int d = 0; d < 3; d++)
            X0s[tid * LDX0 + d] = xyz[(size_t)g * 3 + d] - xyz[(size_t)s * 3 + d];
    }
    const float4* feat4 = reinterpret_cast<const float4*>(feat);
    for (int i = tid; i < ROWS * 16; i += NT) {
        int r = i & 63, c = i >> 6;
        float4 v = feat4[(size_t)gidx[r] * 16 + c];
        float* dst = X0s + r * LDX0 + 3 + c * 4;
        dst[0] = v.x; dst[1] = v.y; dst[2] = v.z; dst[3] = v.w;
    }
    // first chunk-loop __syncthreads orders gather before compute

    // ---- L1: 67 -> 128 (3 chunks, global idx 0..2) ----
    {
        ull acc[RPW][2];
#pragma unroll
        for (int r = 0; r < RPW; r++) { acc[r][0] = 0ull; acc[r][1] = 0ull; }
        for (int ch = 0; ch < 3; ch++) {
            CP_WAIT0; __syncthreads();
            if (ch == 0)      stage<128>(WcB[1], W1, 32, 67);
            else if (ch == 1) stage<128>(WcB[0], W1, 64, 67);
            else              stage<128>(WcB[1], W2, 0, 128);
            CP_COMMIT;
            gemm_chunk<128>(X0s, LDX0, ch * CT, WcB[ch & 1], acc);
        }
        ln_epi<128>(acc, b1, g1, be1, H12s);
    }
    // ---- L2: 128 -> 128 (chunks idx 3..6; buffers continue parity) ----
    {
        ull acc[RPW][2];
#pragma unroll
        for (int r = 0; r < RPW; r++) { acc[r][0] = 0ull; acc[r][1] = 0ull; }
        for (int ch = 0; ch < 4; ch++) {
            CP_WAIT0; __syncthreads();
            if (ch < 3) stage<128>(WcB[(4 + ch) & 1], W2, (ch + 1) * CT, 128);
            else        stage<256>(WcB[(4 + ch) & 1], W3, 0, 128);
            CP_COMMIT;
            gemm_chunk<128>(H12s, 128, ch * CT, WcB[(3 + ch) & 1], acc);
        }
        ln_epi<128>(acc, b2, g2, be2, H12s);  // in place H1 -> H2 (warp-private rows)
    }
    // ---- L3: 128 -> 256 (chunks idx 7..10) ----
    ull acc3[RPW][4];
    {
#pragma unroll
        for (int r = 0; r < RPW; r++)
#pragma unroll
            for (int p = 0; p < 4; p++) acc3[r][p] = 0ull;
        for (int ch = 0; ch < 4; ch++) {
            CP_WAIT0; __syncthreads();
            if (ch < 3) stage<256>(WcB[(8 + ch) & 1], W3, (ch + 1) * CT, 128);
            else        stage<256>(WcB[(8 + ch) & 1], Wa1 + 3 * 256, 0, 256);
            CP_COMMIT;
            gemm_chunk<256>(H12s, 128, ch * CT, WcB[(7 + ch) & 1], acc3);
        }
        ln_epi<256>(acc3, b3, g3, be3, H3s);
    }
    // ---- attention: score = relu([rel,h3] @ Wa1 + ba1) . Wa2 + ba2 ----
    {
#pragma unroll
        for (int r = 0; r < RPW; r++)
#pragma unroll
            for (int p = 0; p < 4; p++) acc3[r][p] = 0ull;
        // rel part (3 cols), weights direct from global (L2-resident)
#pragma unroll
        for (int c = 0; c < 3; c++) {
            ull w[2][2];
#pragma unroll
            for (int b = 0; b < 2; b++) {
                ulonglong2 wv = *reinterpret_cast<const ulonglong2*>(Wa1 + c * 256 + b * 128 + lane * 4);
                w[b][0] = wv.x; w[b][1] = wv.y;
            }
#pragma unroll
            for (int r = 0; r < RPW; r++) {
                float x = X0s[(r0 + r) * LDX0 + c];
                ull xd = pk2(x, x);
#pragma unroll
                for (int b = 0; b < 2; b++) {
                    fma2(acc3[r][b * 2 + 0], xd, w[b][0]);
                    fma2(acc3[r][b * 2 + 1], xd, w[b][1]);
                }
            }
        }
        // h3 part (chunks idx 11..18)
        for (int ch = 0; ch < 8; ch++) {
            CP_WAIT0; __syncthreads();
            if (ch < 7) { stage<256>(WcB[(12 + ch) & 1], Wa1 + 3 * 256, (ch + 1) * CT, 256); CP_COMMIT; }
            gemm_chunk<256>(H3s, 256, ch * CT, WcB[(11 + ch) & 1], acc3);
        }
        // epilogue: relu + dot with Wa2
        ull bp[2][2], ap[2][2];
#pragma unroll
        for (int b = 0; b < 2; b++) {
            ulonglong2 t;
            t = *reinterpret_cast<const ulonglong2*>(ba1 + b * 128 + lane * 4); bp[b][0] = t.x; bp[b][1] = t.y;
            t = *reinterpret_cast<const ulonglong2*>(Wa2 + b * 128 + lane * 4); ap[b][0] = t.x; ap[b][1] = t.y;
        }
        const float bb2 = ba2[0];
#pragma unroll
        for (int r = 0; r < RPW; r++) {
            float sc = 0.f;
#pragma unroll
            for (int b = 0; b < 2; b++)
#pragma unroll
                for (int p = 0; p < 2; p++) {
                    float vl, vh, al, ah;
                    up2(add2(acc3[r][b * 2 + p], bp[b][p]), vl, vh);
                    up2(ap[b][p], al, ah);
                    sc = fmaf(fmaxf(vl, 0.f), al, sc);
                    sc = fmaf(fmaxf(vh, 0.f), ah, sc);
                }
            sc = warp_sum(sc);
            if (lane == 0) scores[r0 + r] = sc + bb2;
        }
    }
    __syncthreads();

    // ---- softmax over K (warp 0,1 -> query 0,1) ----
    if (warp < MB) {
        float v = scores[warp * KNB + lane];
        float mx = v;
#pragma unroll
        for (int o = 16; o > 0; o >>= 1) mx = fmaxf(mx, __shfl_xor_sync(0xffffffffu, mx, o));
        float e = __expf(v - mx);
        float s = warp_sum(e);
        wgt[warp * KNB + lane] = e / s;
    }
    __syncthreads();

    // ---- weighted sum over K: half the CTA per query ----
    {
        int c = tid & 255, q = tid >> 8;
        float a = 0.f;
        const float* wq = wgt + q * KNB;
        const float* hq = H3s + q * KNB * 256;
#pragma unroll 8
        for (int k = 0; k < KNB; k++)
            a = fmaf(wq[k], hq[k * 256 + c], a);
        wsum[q * 256 + c] = a;
    }
    __syncthreads();

    // ---- output projection: half the CTA per query ----
    {
        int c = tid & 255, q = tid >> 8;
        float o = bo[c];
        const float* wq = wsum + q * 256;
#pragma unroll 4
        for (int k = 0; k < 256; k++)
            o = fmaf(wq[k], Wo[(size_t)k * 256 + c], o);
        out_feat[(size_t)(m0 + q) * 256 + c] = o;
    }

    if (out_xyz != nullptr && tid < MB * 3) {
        int mi = tid / 3, d = tid % 3;
        int s = scanidx[m0 + mi];
        out_xyz[(size_t)(m0 + mi) * 3 + d] = xyz[(size_t)s * 3 + d];
    }
}

extern "C" void kernel_launch(void* const* d_in, const int* in_sizes, int n_in,
                              void* d_out, int out_size) {
    const float* xyz       = (const float*)d_in[0];
    const float* feat      = (const float*)d_in[1];
    const int*   scanidx   = (const int*)d_in[2];
    const int*   group_idx = (const int*)d_in[3];
    const float* W1  = (const float*)d_in[4];
    const float* b1  = (const float*)d_in[5];
    const float* g1  = (const float*)d_in[6];
    const float* be1 = (const float*)d_in[7];
    const float* W2  = (const float*)d_in[8];
    const float* b2  = (const float*)d_in[9];
    const float* g2  = (const float*)d_in[10];
    const float* be2 = (const float*)d_in[11];
    const float* W3  = (const float*)d_in[12];
    const float* b3  = (const float*)d_in[13];
    const float* g3  = (const float*)d_in[14];
    const float* be3 = (const float*)d_in[15];
    const float* Wa1 = (const float*)d_in[16];
    const float* ba1 = (const float*)d_in[17];
    const float* Wa2 = (const float*)d_in[18];
    const float* ba2 = (const float*)d_in[19];
    const float* Wo  = (const float*)d_in[20];
    const float* bo  = (const float*)d_in[21];

    const int M = in_sizes[2];

    float* out_xyz  = nullptr;
    float* out_feat = (float*)d_out;
    if (out_size == M * 259) {
        out_xyz  = (float*)d_out;
        out_feat = (float*)d_out + (size_t)M * 3;
    }

    const size_t smem_bytes =
        (ROWS * LDX0 + ROWS * 128 + ROWS * 256 + 2 * CT * 256 + ROWS * 2 + MB * 256) * sizeof(float)
        + ROWS * sizeof(int);

    cudaFuncSetAttribute(sa_fused_kernel,
                         cudaFuncAttributeMaxDynamicSharedMemorySize, (int)smem_bytes);

    sa_fused_kernel<<<M / MB, NT, smem_bytes>>>(
        xyz, feat, scanidx, group_idx,
        W1, b1, g1, be1, W2, b2, g2, be2, W3, b3, g3, be3,
        Wa1, ba1, Wa2, ba2, Wo, bo,
        out_xyz, out_feat);
}

// round 5
// speedup vs baseline: 1.0187x; 1.0187x over previous
#include <cuda_runtime.h>
#include <cstdint>

// Round 5 (= round 4 resubmit after infra failure): 16 warps, column-split.
// Warp (wr, ch) = (warp&7, warp>>3): rows wr*8..wr*8+7, column half ch.
// Weight reuse per LDS stays 8 rows (round-2 crossbar ratio) while keeping
// 4 warps/SMSP for latency hiding. Packed f32x2 FMA + cp.async double buffering.

#define NT 512
#define MB 2
#define KNB 32
#define ROWS 64
#define RPW 8            // rows per warp
#define CT 32            // weight rows per staged chunk
#define LDX0 96

typedef unsigned long long ull;

__device__ __forceinline__ ull pk2(float a, float b) {
    ull r; asm("mov.b64 %0,{%1,%2};" : "=l"(r) : "f"(a), "f"(b)); return r;
}
__device__ __forceinline__ void up2(ull v, float& a, float& b) {
    asm("mov.b64 {%0,%1},%2;" : "=f"(a), "=f"(b) : "l"(v));
}
__device__ __forceinline__ ull add2(ull a, ull b) {
    ull r; asm("add.rn.f32x2 %0,%1,%2;" : "=l"(r) : "l"(a), "l"(b)); return r;
}
__device__ __forceinline__ void fma2(ull& d, ull a, ull b) {
    asm("fma.rn.f32x2 %0,%1,%2,%0;" : "+l"(d) : "l"(a), "l"(b));
}
__device__ __forceinline__ ull fma2r(ull a, ull b, ull c) {
    ull r; asm("fma.rn.f32x2 %0,%1,%2,%3;" : "=l"(r) : "l"(a), "l"(b), "l"(c)); return r;
}

#define CP_COMMIT asm volatile("cp.async.commit_group;")
#define CP_WAIT0  asm volatile("cp.async.wait_group 0;")

__device__ __forceinline__ void cpa16(float* dst, const float* src) {
    unsigned d = (unsigned)__cvta_generic_to_shared(dst);
    asm volatile("cp.async.ca.shared.global [%0], [%1], 16;" :: "r"(d), "l"(src));
}

__device__ __forceinline__ float warp_sum(float v) {
#pragma unroll
    for (int o = 16; o > 0; o >>= 1) v += __shfl_xor_sync(0xffffffffu, v, o);
    return v;
}
__device__ __forceinline__ ull warp_sum2(ull v) {
#pragma unroll
    for (int o = 16; o > 0; o >>= 1) v = add2(v, __shfl_xor_sync(0xffffffffu, v, o));
    return v;
}

// Stage CT rows x FO cols of W (rows >= FI zero-filled) into smem via cp.async.
template <int FO>
__device__ __forceinline__ void stage(float* buf, const float* __restrict__ W,
                                      int c0, int FI) {
    constexpr int VPR = FO / 4;
    constexpr int NV  = CT * VPR;
    const int tid = threadIdx.x;
#pragma unroll
    for (int i = tid; i < NV; i += NT) {
        int row = i / VPR;
        int gc  = c0 + row;
        if (gc < FI) cpa16(buf + i * 4, W + (size_t)gc * FO + (i % VPR) * 4);
        else         *reinterpret_cast<float4*>(buf + i * 4) = make_float4(0.f, 0.f, 0.f, 0.f);
    }
}

// Column-split GEMM chunk. NP = packed pairs per lane = FO/128.
// Lane owns cols [ch*FO/2 + lane*2*NP, +2*NP).
template <int FO>
__device__ __forceinline__ void gemm_chunk(const float* Xs, int ldx, int c0,
                                           const float* Wc, ull (*acc)[FO / 128]) {
    constexpr int NP = FO / 128;
    const int lane = threadIdx.x & 31, warp = threadIdx.x >> 5;
    const int r0   = (warp & 7) * RPW;
    const int wcol = (warp >> 3) * (FO / 2) + lane * 2 * NP;
    const float* wbase = Wc + wcol;
#pragma unroll 4
    for (int c = 0; c < CT; c += 4) {
        float4 xv[RPW];
#pragma unroll
        for (int r = 0; r < RPW; r++)
            xv[r] = *reinterpret_cast<const float4*>(Xs + (r0 + r) * ldx + c0 + c);
#pragma unroll
        for (int cc = 0; cc < 4; cc++) {
            ull w[NP];
            if (NP == 1) {
                w[0] = *reinterpret_cast<const ull*>(wbase + (c + cc) * FO);
            } else {
                ulonglong2 t = *reinterpret_cast<const ulonglong2*>(wbase + (c + cc) * FO);
                w[0] = t.x; w[1] = t.y;
            }
#pragma unroll
            for (int r = 0; r < RPW; r++) {
                float x = (cc == 0) ? xv[r].x : (cc == 1) ? xv[r].y : (cc == 2) ? xv[r].z : xv[r].w;
                ull xd = pk2(x, x);
#pragma unroll
                for (int p = 0; p < NP; p++) fma2(acc[r][p], xd, w[p]);
            }
        }
    }
}

// LayerNorm+ReLU epilogue with cross-warp (2-way) reduction via smem red buffer.
// red layout: red[row*2 + colHalf] = float2(partial_sum, partial_sumsq)
template <int FO>
__device__ __forceinline__ void ln_epi(ull (*acc)[FO / 128],
                                       const float* __restrict__ b, const float* __restrict__ g,
                                       const float* __restrict__ be, float* Ys, float2* red) {
    constexpr int NP = FO / 128;
    const int lane = threadIdx.x & 31, warp = threadIdx.x >> 5;
    const int r0   = (warp & 7) * RPW;
    const int chh  = warp >> 3;
    const int wcol = chh * (FO / 2) + lane * 2 * NP;

    ull bp[NP], gp[NP], bep[NP];
    if (NP == 1) {
        bp[0]  = *reinterpret_cast<const ull*>(b + wcol);
        gp[0]  = *reinterpret_cast<const ull*>(g + wcol);
        bep[0] = *reinterpret_cast<const ull*>(be + wcol);
    } else {
        ulonglong2 t;
        t = *reinterpret_cast<const ulonglong2*>(b + wcol);  bp[0] = t.x;  bp[1] = t.y;
        t = *reinterpret_cast<const ulonglong2*>(g + wcol);  gp[0] = t.x;  gp[1] = t.y;
        t = *reinterpret_cast<const ulonglong2*>(be + wcol); bep[0] = t.x; bep[1] = t.y;
    }
#pragma unroll
    for (int r = 0; r < RPW; r++) {
        ull s = 0ull, q = 0ull;
#pragma unroll
        for (int p = 0; p < NP; p++) {
            ull v = add2(acc[r][p], bp[p]);
            acc[r][p] = v;
            s = add2(s, v);
            q = fma2r(v, v, q);
        }
        float sl, sh, ql, qh; up2(s, sl, sh); up2(q, ql, qh);
        ull sq = warp_sum2(pk2(sl + sh, ql + qh));
        if (lane == 0) {
            float S, Q; up2(sq, S, Q);
            red[(r0 + r) * 2 + chh] = make_float2(S, Q);
        }
    }
    __syncthreads();
    const float invFO = 1.f / (float)FO;
#pragma unroll
    for (int r = 0; r < RPW; r++) {
        float2 p0 = red[(r0 + r) * 2 + 0];
        float2 p1 = red[(r0 + r) * 2 + 1];
        float S = p0.x + p1.x, Q = p0.y + p1.y;
        float mean = S * invFO;
        float var  = fmaxf(Q * invFO - mean * mean, 0.f);
        float inv  = rsqrtf(var + 1e-5f);
        ull vInv = pk2(inv, inv), vOff = pk2(-mean * inv, -mean * inv);
        if (NP == 1) {
            ull t0 = fma2r(fma2r(acc[r][0], vInv, vOff), gp[0], bep[0]);
            float2 o; up2(t0, o.x, o.y);
            o.x = fmaxf(o.x, 0.f); o.y = fmaxf(o.y, 0.f);
            *reinterpret_cast<float2*>(Ys + (r0 + r) * FO + wcol) = o;
        } else {
            ull t0 = fma2r(fma2r(acc[r][0], vInv, vOff), gp[0], bep[0]);
            ull t1 = fma2r(fma2r(acc[r][1], vInv, vOff), gp[1], bep[1]);
            float4 o; up2(t0, o.x, o.y); up2(t1, o.z, o.w);
            o.x = fmaxf(o.x, 0.f); o.y = fmaxf(o.y, 0.f);
            o.z = fmaxf(o.z, 0.f); o.w = fmaxf(o.w, 0.f);
            *reinterpret_cast<float4*>(Ys + (r0 + r) * FO + wcol) = o;
        }
    }
}

extern __shared__ float smem[];

__global__ __launch_bounds__(NT, 1)
void sa_fused_kernel(const float* __restrict__ xyz, const float* __restrict__ feat,
                     const int* __restrict__ scanidx, const int* __restrict__ group_idx,
                     const float* __restrict__ W1, const float* __restrict__ b1,
                     const float* __restrict__ g1, const float* __restrict__ be1,
                     const float* __restrict__ W2, const float* __restrict__ b2,
                     const float* __restrict__ g2, const float* __restrict__ be2,
                     const float* __restrict__ W3, const float* __restrict__ b3,
                     const float* __restrict__ g3, const float* __restrict__ be3,
                     const float* __restrict__ Wa1, const float* __restrict__ ba1,
                     const float* __restrict__ Wa2, const float* __restrict__ ba2,
                     const float* __restrict__ Wo, const float* __restrict__ bo,
                     float* __restrict__ out_xyz, float* __restrict__ out_feat) {
    float* X0s    = smem;                        // 64*96
    float* H12s   = X0s + ROWS * LDX0;           // 64*128
    float* H3s    = H12s + ROWS * 128;           // 64*256
    float* Wc0    = H3s + ROWS * 256;            // 32*256
    float* Wc1    = Wc0 + CT * 256;              // 32*256
    float2* red   = (float2*)(Wc1 + CT * 256);   // 64*2 float2 = 256 floats
    float* scoreP = (float*)(red + ROWS * 2);    // 64*2 partials
    float* wgt    = scoreP + ROWS * 2;           // 64
    float* wsum   = wgt + ROWS;                  // 2*256
    int*   gidx   = (int*)(wsum + MB * 256);     // 64

    float* WcB[2] = { Wc0, Wc1 };

    const int tid  = threadIdx.x;
    const int lane = tid & 31, warp = tid >> 5;
    const int r0   = (warp & 7) * RPW;
    const int chh  = warp >> 3;
    const int m0   = blockIdx.x * MB;

    stage<128>(WcB[0], W1, 0, 67);
    CP_COMMIT;

    // ---- gather ----
    for (int i = tid; i < ROWS * LDX0; i += NT) X0s[i] = 0.f;
    if (tid < ROWS) gidx[tid] = group_idx[(size_t)(m0 + (tid >> 5)) * KNB + (tid & 31)];
    __syncthreads();
    if (tid < ROWS) {
        int g = gidx[tid];
        int s = scanidx[m0 + (tid >> 5)];
#pragma unroll
        for (int d = 0; d < 3; d++)
            X0s[tid * LDX0 + d] = xyz[(size_t)g * 3 + d] - xyz[(size_t)s * 3 + d];
    }
    const float4* feat4 = reinterpret_cast<const float4*>(feat);
    for (int i = tid; i < ROWS * 16; i += NT) {
        int r = i & 63, c = i >> 6;
        float4 v = feat4[(size_t)gidx[r] * 16 + c];
        float* dst = X0s + r * LDX0 + 3 + c * 4;
        dst[0] = v.x; dst[1] = v.y; dst[2] = v.z; dst[3] = v.w;
    }

    // ---- L1: 67 -> 128 ----
    {
        ull acc[RPW][1];
#pragma unroll
        for (int r = 0; r < RPW; r++) acc[r][0] = 0ull;
        for (int ch = 0; ch < 3; ch++) {
            CP_WAIT0; __syncthreads();
            if (ch == 0)      stage<128>(WcB[1], W1, 32, 67);
            else if (ch == 1) stage<128>(WcB[0], W1, 64, 67);
            else              stage<128>(WcB[1], W2, 0, 128);
            CP_COMMIT;
            gemm_chunk<128>(X0s, LDX0, ch * CT, WcB[ch & 1], acc);
        }
        ln_epi<128>(acc, b1, g1, be1, H12s, red);
    }
    // ---- L2: 128 -> 128 ----
    {
        ull acc[RPW][1];
#pragma unroll
        for (int r = 0; r < RPW; r++) acc[r][0] = 0ull;
        for (int ch = 0; ch < 4; ch++) {
            CP_WAIT0; __syncthreads();
            if (ch < 3) stage<128>(WcB[(4 + ch) & 1], W2, (ch + 1) * CT, 128);
            else        stage<256>(WcB[(4 + ch) & 1], W3, 0, 128);
            CP_COMMIT;
            gemm_chunk<128>(H12s, 128, ch * CT, WcB[(3 + ch) & 1], acc);
        }
        ln_epi<128>(acc, b2, g2, be2, H12s, red);  // in-place H1 -> H2
    }
    // ---- L3: 128 -> 256 ----
    ull acc3[RPW][2];
    {
#pragma unroll
        for (int r = 0; r < RPW; r++) { acc3[r][0] = 0ull; acc3[r][1] = 0ull; }
        for (int ch = 0; ch < 4; ch++) {
            CP_WAIT0; __syncthreads();
            if (ch < 3) stage<256>(WcB[(8 + ch) & 1], W3, (ch + 1) * CT, 128);
            else        stage<256>(WcB[(8 + ch) & 1], Wa1 + 3 * 256, 0, 256);
            CP_COMMIT;
            gemm_chunk<256>(H12s, 128, ch * CT, WcB[(7 + ch) & 1], acc3);
        }
        ln_epi<256>(acc3, b3, g3, be3, H3s, red);
    }
    // ---- attention scores ----
    {
        const int wcol = chh * 128 + lane * 4;
#pragma unroll
        for (int r = 0; r < RPW; r++) { acc3[r][0] = 0ull; acc3[r][1] = 0ull; }
#pragma unroll
        for (int c = 0; c < 3; c++) {
            ulonglong2 t = *reinterpret_cast<const ulonglong2*>(Wa1 + c * 256 + wcol);
#pragma unroll
            for (int r = 0; r < RPW; r++) {
                float x = X0s[(r0 + r) * LDX0 + c];
                ull xd = pk2(x, x);
                fma2(acc3[r][0], xd, t.x);
                fma2(acc3[r][1], xd, t.y);
            }
        }
        for (int ch = 0; ch < 8; ch++) {
            CP_WAIT0; __syncthreads();
            if (ch < 7) { stage<256>(WcB[(12 + ch) & 1], Wa1 + 3 * 256, (ch + 1) * CT, 256); CP_COMMIT; }
            gemm_chunk<256>(H3s, 256, ch * CT, WcB[(11 + ch) & 1], acc3);
        }
        ulonglong2 bt = *reinterpret_cast<const ulonglong2*>(ba1 + wcol);
        ulonglong2 at = *reinterpret_cast<const ulonglong2*>(Wa2 + wcol);
        ull bp[2] = { bt.x, bt.y }, ap[2] = { at.x, at.y };
#pragma unroll
        for (int r = 0; r < RPW; r++) {
            float sc = 0.f;
#pragma unroll
            for (int p = 0; p < 2; p++) {
                float vl, vh, al, ah;
                up2(add2(acc3[r][p], bp[p]), vl, vh);
                up2(ap[p], al, ah);
                sc = fmaf(fmaxf(vl, 0.f), al, sc);
                sc = fmaf(fmaxf(vh, 0.f), ah, sc);
            }
            sc = warp_sum(sc);
            if (lane == 0) scoreP[(r0 + r) * 2 + chh] = sc;
        }
    }
    __syncthreads();

    // ---- softmax over K ----
    if (warp < MB) {
        float v = scoreP[(warp * KNB + lane) * 2] + scoreP[(warp * KNB + lane) * 2 + 1] + ba2[0];
        float mx = v;
#pragma unroll
        for (int o = 16; o > 0; o >>= 1) mx = fmaxf(mx, __shfl_xor_sync(0xffffffffu, mx, o));
        float e = __expf(v - mx);
        float s = warp_sum(e);
        wgt[warp * KNB + lane] = e / s;
    }
    __syncthreads();

    // ---- weighted sum over K: half CTA per query ----
    {
        int c = tid & 255, q = tid >> 8;
        float a = 0.f;
        const float* wq = wgt + q * KNB;
        const float* hq = H3s + q * KNB * 256;
#pragma unroll 8
        for (int k = 0; k < KNB; k++)
            a = fmaf(wq[k], hq[k * 256 + c], a);
        wsum[q * 256 + c] = a;
    }
    __syncthreads();

    // ---- output projection ----
    {
        int c = tid & 255, q = tid >> 8;
        float o = bo[c];
        const float* wq = wsum + q * 256;
#pragma unroll 4
        for (int k = 0; k < 256; k++)
            o = fmaf(wq[k], Wo[(size_t)k * 256 + c], o);
        out_feat[(size_t)(m0 + q) * 256 + c] = o;
    }

    if (out_xyz != nullptr && tid < MB * 3) {
        int mi = tid / 3, d = tid % 3;
        int s = scanidx[m0 + mi];
        out_xyz[(size_t)(m0 + mi) * 3 + d] = xyz[(size_t)s * 3 + d];
    }
}

extern "C" void kernel_launch(void* const* d_in, const int* in_sizes, int n_in,
                              void* d_out, int out_size) {
    const float* xyz       = (const float*)d_in[0];
    const float* feat      = (const float*)d_in[1];
    const int*   scanidx   = (const int*)d_in[2];
    const int*   group_idx = (const int*)d_in[3];
    const float* W1  = (const float*)d_in[4];
    const float* b1  = (const float*)d_in[5];
    const float* g1  = (const float*)d_in[6];
    const float* be1 = (const float*)d_in[7];
    const float* W2  = (const float*)d_in[8];
    const float* b2  = (const float*)d_in[9];
    const float* g2  = (const float*)d_in[10];
    const float* be2 = (const float*)d_in[11];
    const float* W3  = (const float*)d_in[12];
    const float* b3  = (const float*)d_in[13];
    const float* g3  = (const float*)d_in[14];
    const float* be3 = (const float*)d_in[15];
    const float* Wa1 = (const float*)d_in[16];
    const float* ba1 = (const float*)d_in[17];
    const float* Wa2 = (const float*)d_in[18];
    const float* ba2 = (const float*)d_in[19];
    const float* Wo  = (const float*)d_in[20];
    const float* bo  = (const float*)d_in[21];

    const int M = in_sizes[2];

    float* out_xyz  = nullptr;
    float* out_feat = (float*)d_out;
    if (out_size == M * 259) {
        out_xyz  = (float*)d_out;
        out_feat = (float*)d_out + (size_t)M * 3;
    }

    const size_t smem_bytes =
        (ROWS * LDX0 + ROWS * 128 + ROWS * 256 + 2 * CT * 256
         + ROWS * 4 /*red*/ + ROWS * 2 /*scoreP*/ + ROWS /*wgt*/ + MB * 256) * sizeof(float)
        + ROWS * sizeof(int);

    cudaFuncSetAttribute(sa_fused_kernel,
                         cudaFuncAttributeMaxDynamicSharedMemorySize, (int)smem_bytes);

    sa_fused_kernel<<<M / MB, NT, smem_bytes>>>(
        xyz, feat, scanidx, group_idx,
        W1, b1, g1, be1, W2, b2, g2, be2, W3, b3, g3, be3,
        Wa1, ba1, Wa2, ba2, Wo, bo,
        out_xyz, out_feat);
}

// round 6
// speedup vs baseline: 1.0217x; 1.0030x over previous
#include <cuda_runtime.h>
#include <cstdint>

// Round 5 (= round 4 resubmit after infra failure): 16 warps, column-split.
// Warp (wr, ch) = (warp&7, warp>>3): rows wr*8..wr*8+7, column half ch.
// Weight reuse per LDS stays 8 rows (round-2 crossbar ratio) while keeping
// 4 warps/SMSP for latency hiding. Packed f32x2 FMA + cp.async double buffering.

#define NT 512
#define MB 2
#define KNB 32
#define ROWS 64
#define RPW 8            // rows per warp
#define CT 32            // weight rows per staged chunk
#define LDX0 96

typedef unsigned long long ull;

__device__ __forceinline__ ull pk2(float a, float b) {
    ull r; asm("mov.b64 %0,{%1,%2};" : "=l"(r) : "f"(a), "f"(b)); return r;
}
__device__ __forceinline__ void up2(ull v, float& a, float& b) {
    asm("mov.b64 {%0,%1},%2;" : "=f"(a), "=f"(b) : "l"(v));
}
__device__ __forceinline__ ull add2(ull a, ull b) {
    ull r; asm("add.rn.f32x2 %0,%1,%2;" : "=l"(r) : "l"(a), "l"(b)); return r;
}
__device__ __forceinline__ void fma2(ull& d, ull a, ull b) {
    asm("fma.rn.f32x2 %0,%1,%2,%0;" : "+l"(d) : "l"(a), "l"(b));
}
__device__ __forceinline__ ull fma2r(ull a, ull b, ull c) {
    ull r; asm("fma.rn.f32x2 %0,%1,%2,%3;" : "=l"(r) : "l"(a), "l"(b), "l"(c)); return r;
}

#define CP_COMMIT asm volatile("cp.async.commit_group;")
#define CP_WAIT0  asm volatile("cp.async.wait_group 0;")

__device__ __forceinline__ void cpa16(float* dst, const float* src) {
    unsigned d = (unsigned)__cvta_generic_to_shared(dst);
    asm volatile("cp.async.ca.shared.global [%0], [%1], 16;" :: "r"(d), "l"(src));
}

__device__ __forceinline__ float warp_sum(float v) {
#pragma unroll
    for (int o = 16; o > 0; o >>= 1) v += __shfl_xor_sync(0xffffffffu, v, o);
    return v;
}
__device__ __forceinline__ ull warp_sum2(ull v) {
#pragma unroll
    for (int o = 16; o > 0; o >>= 1) v = add2(v, __shfl_xor_sync(0xffffffffu, v, o));
    return v;
}

// Stage CT rows x FO cols of W (rows >= FI zero-filled) into smem via cp.async.
template <int FO>
__device__ __forceinline__ void stage(float* buf, const float* __restrict__ W,
                                      int c0, int FI) {
    constexpr int VPR = FO / 4;
    constexpr int NV  = CT * VPR;
    const int tid = threadIdx.x;
#pragma unroll
    for (int i = tid; i < NV; i += NT) {
        int row = i / VPR;
        int gc  = c0 + row;
        if (gc < FI) cpa16(buf + i * 4, W + (size_t)gc * FO + (i % VPR) * 4);
        else         *reinterpret_cast<float4*>(buf + i * 4) = make_float4(0.f, 0.f, 0.f, 0.f);
    }
}

// Column-split GEMM chunk. NP = packed pairs per lane = FO/128.
// Lane owns cols [ch*FO/2 + lane*2*NP, +2*NP).
template <int FO>
__device__ __forceinline__ void gemm_chunk(const float* Xs, int ldx, int c0,
                                           const float* Wc, ull (*acc)[FO / 128]) {
    constexpr int NP = FO / 128;
    const int lane = threadIdx.x & 31, warp = threadIdx.x >> 5;
    const int r0   = (warp & 7) * RPW;
    const int wcol = (warp >> 3) * (FO / 2) + lane * 2 * NP;
    const float* wbase = Wc + wcol;
#pragma unroll 4
    for (int c = 0; c < CT; c += 4) {
        float4 xv[RPW];
#pragma unroll
        for (int r = 0; r < RPW; r++)
            xv[r] = *reinterpret_cast<const float4*>(Xs + (r0 + r) * ldx + c0 + c);
#pragma unroll
        for (int cc = 0; cc < 4; cc++) {
            ull w[NP];
            if (NP == 1) {
                w[0] = *reinterpret_cast<const ull*>(wbase + (c + cc) * FO);
            } else {
                ulonglong2 t = *reinterpret_cast<const ulonglong2*>(wbase + (c + cc) * FO);
                w[0] = t.x; w[1] = t.y;
            }
#pragma unroll
            for (int r = 0; r < RPW; r++) {
                float x = (cc == 0) ? xv[r].x : (cc == 1) ? xv[r].y : (cc == 2) ? xv[r].z : xv[r].w;
                ull xd = pk2(x, x);
#pragma unroll
                for (int p = 0; p < NP; p++) fma2(acc[r][p], xd, w[p]);
            }
        }
    }
}

// LayerNorm+ReLU epilogue with cross-warp (2-way) reduction via smem red buffer.
// red layout: red[row*2 + colHalf] = float2(partial_sum, partial_sumsq)
template <int FO>
__device__ __forceinline__ void ln_epi(ull (*acc)[FO / 128],
                                       const float* __restrict__ b, const float* __restrict__ g,
                                       const float* __restrict__ be, float* Ys, float2* red) {
    constexpr int NP = FO / 128;
    const int lane = threadIdx.x & 31, warp = threadIdx.x >> 5;
    const int r0   = (warp & 7) * RPW;
    const int chh  = warp >> 3;
    const int wcol = chh * (FO / 2) + lane * 2 * NP;

    ull bp[NP], gp[NP], bep[NP];
    if (NP == 1) {
        bp[0]  = *reinterpret_cast<const ull*>(b + wcol);
        gp[0]  = *reinterpret_cast<const ull*>(g + wcol);
        bep[0] = *reinterpret_cast<const ull*>(be + wcol);
    } else {
        ulonglong2 t;
        t = *reinterpret_cast<const ulonglong2*>(b + wcol);  bp[0] = t.x;  bp[1] = t.y;
        t = *reinterpret_cast<const ulonglong2*>(g + wcol);  gp[0] = t.x;  gp[1] = t.y;
        t = *reinterpret_cast<const ulonglong2*>(be + wcol); bep[0] = t.x; bep[1] = t.y;
    }
#pragma unroll
    for (int r = 0; r < RPW; r++) {
        ull s = 0ull, q = 0ull;
#pragma unroll
        for (int p = 0; p < NP; p++) {
            ull v = add2(acc[r][p], bp[p]);
            acc[r][p] = v;
            s = add2(s, v);
            q = fma2r(v, v, q);
        }
        float sl, sh, ql, qh; up2(s, sl, sh); up2(q, ql, qh);
        ull sq = warp_sum2(pk2(sl + sh, ql + qh));
        if (lane == 0) {
            float S, Q; up2(sq, S, Q);
            red[(r0 + r) * 2 + chh] = make_float2(S, Q);
        }
    }
    __syncthreads();
    const float invFO = 1.f / (float)FO;
#pragma unroll
    for (int r = 0; r < RPW; r++) {
        float2 p0 = red[(r0 + r) * 2 + 0];
        float2 p1 = red[(r0 + r) * 2 + 1];
        float S = p0.x + p1.x, Q = p0.y + p1.y;
        float mean = S * invFO;
        float var  = fmaxf(Q * invFO - mean * mean, 0.f);
        float inv  = rsqrtf(var + 1e-5f);
        ull vInv = pk2(inv, inv), vOff = pk2(-mean * inv, -mean * inv);
        if (NP == 1) {
            ull t0 = fma2r(fma2r(acc[r][0], vInv, vOff), gp[0], bep[0]);
            float2 o; up2(t0, o.x, o.y);
            o.x = fmaxf(o.x, 0.f); o.y = fmaxf(o.y, 0.f);
            *reinterpret_cast<float2*>(Ys + (r0 + r) * FO + wcol) = o;
        } else {
            ull t0 = fma2r(fma2r(acc[r][0], vInv, vOff), gp[0], bep[0]);
            ull t1 = fma2r(fma2r(acc[r][1], vInv, vOff), gp[1], bep[1]);
            float4 o; up2(t0, o.x, o.y); up2(t1, o.z, o.w);
            o.x = fmaxf(o.x, 0.f); o.y = fmaxf(o.y, 0.f);
            o.z = fmaxf(o.z, 0.f); o.w = fmaxf(o.w, 0.f);
            *reinterpret_cast<float4*>(Ys + (r0 + r) * FO + wcol) = o;
        }
    }
}

extern __shared__ float smem[];

__global__ __launch_bounds__(NT, 1)
void sa_fused_kernel(const float* __restrict__ xyz, const float* __restrict__ feat,
                     const int* __restrict__ scanidx, const int* __restrict__ group_idx,
                     const float* __restrict__ W1, const float* __restrict__ b1,
                     const float* __restrict__ g1, const float* __restrict__ be1,
                     const float* __restrict__ W2, const float* __restrict__ b2,
                     const float* __restrict__ g2, const float* __restrict__ be2,
                     const float* __restrict__ W3, const float* __restrict__ b3,
                     const float* __restrict__ g3, const float* __restrict__ be3,
                     const float* __restrict__ Wa1, const float* __restrict__ ba1,
                     const float* __restrict__ Wa2, const float* __restrict__ ba2,
                     const float* __restrict__ Wo, const float* __restrict__ bo,
                     float* __restrict__ out_xyz, float* __restrict__ out_feat) {
    float* X0s    = smem;                        // 64*96
    float* H12s   = X0s + ROWS * LDX0;           // 64*128
    float* H3s    = H12s + ROWS * 128;           // 64*256
    float* Wc0    = H3s + ROWS * 256;            // 32*256
    float* Wc1    = Wc0 + CT * 256;              // 32*256
    float2* red   = (float2*)(Wc1 + CT * 256);   // 64*2 float2 = 256 floats
    float* scoreP = (float*)(red + ROWS * 2);    // 64*2 partials
    float* wgt    = scoreP + ROWS * 2;           // 64
    float* wsum   = wgt + ROWS;                  // 2*256
    int*   gidx   = (int*)(wsum + MB * 256);     // 64

    float* WcB[2] = { Wc0, Wc1 };

    const int tid  = threadIdx.x;
    const int lane = tid & 31, warp = tid >> 5;
    const int r0   = (warp & 7) * RPW;
    const int chh  = warp >> 3;
    const int m0   = blockIdx.x * MB;

    stage<128>(WcB[0], W1, 0, 67);
    CP_COMMIT;

    // ---- gather ----
    for (int i = tid; i < ROWS * LDX0; i += NT) X0s[i] = 0.f;
    if (tid < ROWS) gidx[tid] = group_idx[(size_t)(m0 + (tid >> 5)) * KNB + (tid & 31)];
    __syncthreads();
    if (tid < ROWS) {
        int g = gidx[tid];
        int s = scanidx[m0 + (tid >> 5)];
#pragma unroll
        for (int d = 0; d < 3; d++)
            X0s[tid * LDX0 + d] = xyz[(size_t)g * 3 + d] - xyz[(size_t)s * 3 + d];
    }
    const float4* feat4 = reinterpret_cast<const float4*>(feat);
    for (int i = tid; i < ROWS * 16; i += NT) {
        int r = i & 63, c = i >> 6;
        float4 v = feat4[(size_t)gidx[r] * 16 + c];
        float* dst = X0s + r * LDX0 + 3 + c * 4;
        dst[0] = v.x; dst[1] = v.y; dst[2] = v.z; dst[3] = v.w;
    }

    // ---- L1: 67 -> 128 ----
    {
        ull acc[RPW][1];
#pragma unroll
        for (int r = 0; r < RPW; r++) acc[r][0] = 0ull;
        for (int ch = 0; ch < 3; ch++) {
            CP_WAIT0; __syncthreads();
            if (ch == 0)      stage<128>(WcB[1], W1, 32, 67);
            else if (ch == 1) stage<128>(WcB[0], W1, 64, 67);
            else              stage<128>(WcB[1], W2, 0, 128);
            CP_COMMIT;
            gemm_chunk<128>(X0s, LDX0, ch * CT, WcB[ch & 1], acc);
        }
        ln_epi<128>(acc, b1, g1, be1, H12s, red);
    }
    // ---- L2: 128 -> 128 ----
    {
        ull acc[RPW][1];
#pragma unroll
        for (int r = 0; r < RPW; r++) acc[r][0] = 0ull;
        for (int ch = 0; ch < 4; ch++) {
            CP_WAIT0; __syncthreads();
            if (ch < 3) stage<128>(WcB[(4 + ch) & 1], W2, (ch + 1) * CT, 128);
            else        stage<256>(WcB[(4 + ch) & 1], W3, 0, 128);
            CP_COMMIT;
            gemm_chunk<128>(H12s, 128, ch * CT, WcB[(3 + ch) & 1], acc);
        }
        ln_epi<128>(acc, b2, g2, be2, H12s, red);  // in-place H1 -> H2
    }
    // ---- L3: 128 -> 256 ----
    ull acc3[RPW][2];
    {
#pragma unroll
        for (int r = 0; r < RPW; r++) { acc3[r][0] = 0ull; acc3[r][1] = 0ull; }
        for (int ch = 0; ch < 4; ch++) {
            CP_WAIT0; __syncthreads();
            if (ch < 3) stage<256>(WcB[(8 + ch) & 1], W3, (ch + 1) * CT, 128);
            else        stage<256>(WcB[(8 + ch) & 1], Wa1 + 3 * 256, 0, 256);
            CP_COMMIT;
            gemm_chunk<256>(H12s, 128, ch * CT, WcB[(7 + ch) & 1], acc3);
        }
        ln_epi<256>(acc3, b3, g3, be3, H3s, red);
    }
    // ---- attention scores ----
    {
        const int wcol = chh * 128 + lane * 4;
#pragma unroll
        for (int r = 0; r < RPW; r++) { acc3[r][0] = 0ull; acc3[r][1] = 0ull; }
#pragma unroll
        for (int c = 0; c < 3; c++) {
            ulonglong2 t = *reinterpret_cast<const ulonglong2*>(Wa1 + c * 256 + wcol);
#pragma unroll
            for (int r = 0; r < RPW; r++) {
                float x = X0s[(r0 + r) * LDX0 + c];
                ull xd = pk2(x, x);
                fma2(acc3[r][0], xd, t.x);
                fma2(acc3[r][1], xd, t.y);
            }
        }
        for (int ch = 0; ch < 8; ch++) {
            CP_WAIT0; __syncthreads();
            if (ch < 7) { stage<256>(WcB[(12 + ch) & 1], Wa1 + 3 * 256, (ch + 1) * CT, 256); CP_COMMIT; }
            gemm_chunk<256>(H3s, 256, ch * CT, WcB[(11 + ch) & 1], acc3);
        }
        ulonglong2 bt = *reinterpret_cast<const ulonglong2*>(ba1 + wcol);
        ulonglong2 at = *reinterpret_cast<const ulonglong2*>(Wa2 + wcol);
        ull bp[2] = { bt.x, bt.y }, ap[2] = { at.x, at.y };
#pragma unroll
        for (int r = 0; r < RPW; r++) {
            float sc = 0.f;
#pragma unroll
            for (int p = 0; p < 2; p++) {
                float vl, vh, al, ah;
                up2(add2(acc3[r][p], bp[p]), vl, vh);
                up2(ap[p], al, ah);
                sc = fmaf(fmaxf(vl, 0.f), al, sc);
                sc = fmaf(fmaxf(vh, 0.f), ah, sc);
            }
            sc = warp_sum(sc);
            if (lane == 0) scoreP[(r0 + r) * 2 + chh] = sc;
        }
    }
    __syncthreads();

    // ---- softmax over K ----
    if (warp < MB) {
        float v = scoreP[(warp * KNB + lane) * 2] + scoreP[(warp * KNB + lane) * 2 + 1] + ba2[0];
        float mx = v;
#pragma unroll
        for (int o = 16; o > 0; o >>= 1) mx = fmaxf(mx, __shfl_xor_sync(0xffffffffu, mx, o));
        float e = __expf(v - mx);
        float s = warp_sum(e);
        wgt[warp * KNB + lane] = e / s;
    }
    __syncthreads();

    // ---- weighted sum over K: half CTA per query ----
    {
        int c = tid & 255, q = tid >> 8;
        float a = 0.f;
        const float* wq = wgt + q * KNB;
        const float* hq = H3s + q * KNB * 256;
#pragma unroll 8
        for (int k = 0; k < KNB; k++)
            a = fmaf(wq[k], hq[k * 256 + c], a);
        wsum[q * 256 + c] = a;
    }
    __syncthreads();

    // ---- output projection ----
    {
        int c = tid & 255, q = tid >> 8;
        float o = bo[c];
        const float* wq = wsum + q * 256;
#pragma unroll 4
        for (int k = 0; k < 256; k++)
            o = fmaf(wq[k], Wo[(size_t)k * 256 + c], o);
        out_feat[(size_t)(m0 + q) * 256 + c] = o;
    }

    if (out_xyz != nullptr && tid < MB * 3) {
        int mi = tid / 3, d = tid % 3;
        int s = scanidx[m0 + mi];
        out_xyz[(size_t)(m0 + mi) * 3 + d] = xyz[(size_t)s * 3 + d];
    }
}

extern "C" void kernel_launch(void* const* d_in, const int* in_sizes, int n_in,
                              void* d_out, int out_size) {
    const float* xyz       = (const float*)d_in[0];
    const float* feat      = (const float*)d_in[1];
    const int*   scanidx   = (const int*)d_in[2];
    const int*   group_idx = (const int*)d_in[3];
    const float* W1  = (const float*)d_in[4];
    const float* b1  = (const float*)d_in[5];
    const float* g1  = (const float*)d_in[6];
    const float* be1 = (const float*)d_in[7];
    const float* W2  = (const float*)d_in[8];
    const float* b2  = (const float*)d_in[9];
    const float* g2  = (const float*)d_in[10];
    const float* be2 = (const float*)d_in[11];
    const float* W3  = (const float*)d_in[12];
    const float* b3  = (const float*)d_in[13];
    const float* g3  = (const float*)d_in[14];
    const float* be3 = (const float*)d_in[15];
    const float* Wa1 = (const float*)d_in[16];
    const float* ba1 = (const float*)d_in[17];
    const float* Wa2 = (const float*)d_in[18];
    const float* ba2 = (const float*)d_in[19];
    const float* Wo  = (const float*)d_in[20];
    const float* bo  = (const float*)d_in[21];

    const int M = in_sizes[2];

    float* out_xyz  = nullptr;
    float* out_feat = (float*)d_out;
    if (out_size == M * 259) {
        out_xyz  = (float*)d_out;
        out_feat = (float*)d_out + (size_t)M * 3;
    }

    const size_t smem_bytes =
        (ROWS * LDX0 + ROWS * 128 + ROWS * 256 + 2 * CT * 256
         + ROWS * 4 /*red*/ + ROWS * 2 /*scoreP*/ + ROWS /*wgt*/ + MB * 256) * sizeof(float)
        + ROWS * sizeof(int);

    cudaFuncSetAttribute(sa_fused_kernel,
                         cudaFuncAttributeMaxDynamicSharedMemorySize, (int)smem_bytes);

    sa_fused_kernel<<<M / MB, NT, smem_bytes>>>(
        xyz, feat, scanidx, group_idx,
        W1, b1, g1, be1, W2, b2, g2, be2, W3, b3, g3, be3,
        Wa1, ba1, Wa2, ba2, Wo, bo,
        out_xyz, out_feat);
}

// round 8
// speedup vs baseline: 1.3294x; 1.3012x over previous
#include <cuda_runtime.h>
#include <cuda_bf16.h>
#include <cstdint>

// SetAbstraction fused kernel — mma.sync (HMMA) split-bf16 3-pass version.
// tcgen05 is unavailable (harness emits compute_100 PTX), so we use the
// baseline sm_80+ tensor-core path: ldmatrix + mma.sync.m16n8k16 bf16.
// One CTA = 2 query points (64 rows). 512 threads = 16 warps
//   warp = (rowtile = warp&3 [16 rows], colgroup = warp>>2 [FO/4 cols])
// Precision: x = xh + xl (bf16); D += Ah*Bh + Al*Bh + Ah*Bl  (~1.5e-5 rel)

typedef unsigned u32;

#define NTH 512
#define ROWS 64

// ---- SMEM byte offsets ----
#define X0H_O   0u          // [64][88 bf16] stride 176B (11*16, odd)
#define X0L_O   11264u
#define H12H_O  22528u      // [64][136 bf16] stride 272B (17*16, odd)
#define H12L_O  39936u
#define H3H_O   57344u      // [64][264 bf16] stride 528B (33*16, odd)
#define H3L_O   91136u
#define BH0_O   124928u     // B chunk buffers: [256][40 bf16] stride 80B (5*16, odd)
#define BL0_O   145408u
#define BH1_O   165888u
#define BL1_O   186368u
#define RED_O   206848u     // 64*4 float2
#define SCP_O   208896u     // 64*4 float
#define WGT_O   209920u     // 64 float
#define WSM_O   210176u     // 512 float
#define REL_O   212224u     // 64*3 float
#define GIDX_O  212992u     // 64 int
#define SMEM_SZ 213504u

#define LDA_X0  176
#define LDA_H12 272
#define LDA_H3  528
#define LDB     80

__device__ __forceinline__ u32 s2u(const void* p) {
    u32 a; asm("{ .reg .u64 t; cvta.to.shared.u64 t, %1; cvt.u32.u64 %0, t; }" : "=r"(a) : "l"(p));
    return a;
}
__device__ __forceinline__ void ldsm4(u32 a[4], u32 addr) {
    asm volatile("ldmatrix.sync.aligned.m8n8.x4.shared.b16 {%0,%1,%2,%3}, [%4];"
                 : "=r"(a[0]), "=r"(a[1]), "=r"(a[2]), "=r"(a[3]) : "r"(addr));
}
__device__ __forceinline__ void ldsm2(u32 b[2], u32 addr) {
    asm volatile("ldmatrix.sync.aligned.m8n8.x2.shared.b16 {%0,%1}, [%2];"
                 : "=r"(b[0]), "=r"(b[1]) : "r"(addr));
}
__device__ __forceinline__ void mma16816(float c[4], const u32 a[4], const u32 b[2]) {
    asm volatile("mma.sync.aligned.m16n8k16.row.col.f32.bf16.bf16.f32 "
                 "{%0,%1,%2,%3}, {%4,%5,%6,%7}, {%8,%9}, {%0,%1,%2,%3};"
                 : "+f"(c[0]), "+f"(c[1]), "+f"(c[2]), "+f"(c[3])
                 : "r"(a[0]), "r"(a[1]), "r"(a[2]), "r"(a[3]), "r"(b[0]), "r"(b[1]));
}
__device__ __forceinline__ void bsplit2(float y0, float y1, u32& hw, u32& lw) {
    __nv_bfloat16 h0 = __float2bfloat16(y0), h1 = __float2bfloat16(y1);
    __nv_bfloat16 l0 = __float2bfloat16(y0 - __bfloat162float(h0));
    __nv_bfloat16 l1 = __float2bfloat16(y1 - __bfloat162float(h1));
    __nv_bfloat162 a; a.x = h0; a.y = h1; hw = *(u32*)&a;
    __nv_bfloat162 c; c.x = l0; c.y = l1; lw = *(u32*)&c;
}

// GEMM of one staged K-chunk (<=32 k). NTN n-tiles (8 cols each) per warp.
template<int NTN>
__device__ __forceinline__ void chunk_gemm(u32 aH, u32 aL, int lda,
                                           u32 bH, u32 bL,
                                           int k0, int nk, float (*C)[4]) {
    const int lane = threadIdx.x & 31, warp = threadIdx.x >> 5;
    const int rt = warp & 3, cg = warp >> 2;
    const u32 aOff = (u32)((rt * 16 + (lane & 15)) * lda + (lane >> 4) * 16);
    const u32 bOff = (u32)((cg * (NTN * 8) + (lane & 7)) * LDB + ((lane >> 3) & 1) * 16);
    for (int ks = 0; ks < nk; ks++) {
        u32 ah[4], al[4];
        u32 ak = aOff + (u32)((k0 + ks * 16) * 2);
        ldsm4(ah, aH + ak);
        ldsm4(al, aL + ak);
        const u32 kb = (u32)(ks * 32);
#pragma unroll
        for (int nt = 0; nt < NTN; nt++) {
            u32 bh[2], bl[2];
            u32 ba = bOff + (u32)(nt * 8 * LDB) + kb;
            ldsm2(bh, bH + ba);
            ldsm2(bl, bL + ba);
            mma16816(C[nt], ah, bh);
            mma16816(C[nt], al, bh);
            mma16816(C[nt], ah, bl);
        }
    }
}

// Run one GEMM layer: stage B chunks (dbl-buffered, reg-prefetch), accumulate C.
// W is [K_logical rows][N] row-major; rows >= FI are zero.
template<int NTN, int LOG2N>
__device__ __forceinline__ void run_layer(char* sm, u32 sb,
                                          u32 aHo, u32 aLo, int lda,
                                          const float* __restrict__ W, int FI, int K,
                                          float (*C)[4]) {
    constexpr int N  = NTN * 32;
    constexpr int NV = N / 16;              // elements per thread per chunk
    const int tid = threadIdx.x;
    const u32 BHo[2] = { BH0_O, BH1_O };
    const u32 BLo[2] = { BL0_O, BL1_O };
    const int nch = (K + 31) / 32;
    float rg[NV];
    // prefetch chunk 0
#pragma unroll
    for (int j = 0; j < NV; j++) {
        int i = j * NTH + tid, kc = i >> LOG2N, n = i & (N - 1);
        rg[j] = (kc < FI) ? __ldg(W + (size_t)kc * N + n) : 0.f;
    }
    for (int ch = 0; ch < nch; ch++) {
        // store current chunk to smem (split bf16)
#pragma unroll
        for (int j = 0; j < NV; j++) {
            int i = j * NTH + tid, kc = i >> LOG2N, n = i & (N - 1);
            float v = rg[j];
            __nv_bfloat16 h = __float2bfloat16(v);
            __nv_bfloat16 l = __float2bfloat16(v - __bfloat162float(h));
            *(__nv_bfloat16*)(sm + BHo[ch & 1] + n * LDB + kc * 2) = h;
            *(__nv_bfloat16*)(sm + BLo[ch & 1] + n * LDB + kc * 2) = l;
        }
        // prefetch next chunk
        if (ch + 1 < nch) {
            int k0n = (ch + 1) * 32;
#pragma unroll
            for (int j = 0; j < NV; j++) {
                int i = j * NTH + tid, kc = i >> LOG2N, n = i & (N - 1);
                rg[j] = (k0n + kc < FI) ? __ldg(W + (size_t)(k0n + kc) * N + n) : 0.f;
            }
        }
        __syncthreads();
        int nk = K - ch * 32; nk = (nk >= 32) ? 2 : (nk + 15) / 16;
        chunk_gemm<NTN>(sb + aHo, sb + aLo, lda, sb + BHo[ch & 1], sb + BLo[ch & 1],
                        ch * 32, nk, C);
        __syncthreads();
    }
}

// LayerNorm+ReLU epilogue -> split-bf16 dest A buffer.
template<int NTN>
__device__ __forceinline__ void ln_epilogue(char* sm, float (*C)[4],
                                            const float* __restrict__ b,
                                            const float* __restrict__ g,
                                            const float* __restrict__ be,
                                            u32 dHo, u32 dLo, int ldd, float invFO) {
    const int lane = threadIdx.x & 31, warp = threadIdx.x >> 5;
    const int rt = warp & 3, cg = warp >> 2;
    const int r0 = rt * 16 + (lane >> 2);
    const int c0 = cg * (NTN * 8) + (lane & 3) * 2;
    float s0 = 0.f, q0 = 0.f, s1 = 0.f, q1 = 0.f;
#pragma unroll
    for (int nt = 0; nt < NTN; nt++) {
        int c = c0 + nt * 8;
        float b0 = __ldg(b + c), b1 = __ldg(b + c + 1);
        C[nt][0] += b0; C[nt][1] += b1; C[nt][2] += b0; C[nt][3] += b1;
        s0 += C[nt][0] + C[nt][1]; q0 += C[nt][0] * C[nt][0] + C[nt][1] * C[nt][1];
        s1 += C[nt][2] + C[nt][3]; q1 += C[nt][2] * C[nt][2] + C[nt][3] * C[nt][3];
    }
#pragma unroll
    for (int o = 1; o <= 2; o <<= 1) {
        s0 += __shfl_xor_sync(0xffffffffu, s0, o); q0 += __shfl_xor_sync(0xffffffffu, q0, o);
        s1 += __shfl_xor_sync(0xffffffffu, s1, o); q1 += __shfl_xor_sync(0xffffffffu, q1, o);
    }
    float2* red = (float2*)(sm + RED_O);
    if ((lane & 3) == 0) {
        red[r0 * 4 + cg]       = make_float2(s0, q0);
        red[(r0 + 8) * 4 + cg] = make_float2(s1, q1);
    }
    __syncthreads();
    float S0 = 0.f, Q0 = 0.f, S1 = 0.f, Q1 = 0.f;
#pragma unroll
    for (int t = 0; t < 4; t++) {
        float2 p = red[r0 * 4 + t];       S0 += p.x; Q0 += p.y;
        float2 p2 = red[(r0 + 8) * 4 + t]; S1 += p2.x; Q1 += p2.y;
    }
    float m0 = S0 * invFO, i0 = rsqrtf(fmaxf(Q0 * invFO - m0 * m0, 0.f) + 1e-5f);
    float m1 = S1 * invFO, i1 = rsqrtf(fmaxf(Q1 * invFO - m1 * m1, 0.f) + 1e-5f);
#pragma unroll
    for (int nt = 0; nt < NTN; nt++) {
        int c = c0 + nt * 8;
        float g0 = __ldg(g + c), g1 = __ldg(g + c + 1);
        float e0 = __ldg(be + c), e1 = __ldg(be + c + 1);
        float y0 = fmaxf((C[nt][0] - m0) * i0 * g0 + e0, 0.f);
        float y1 = fmaxf((C[nt][1] - m0) * i0 * g1 + e1, 0.f);
        float y2 = fmaxf((C[nt][2] - m1) * i1 * g0 + e0, 0.f);
        float y3 = fmaxf((C[nt][3] - m1) * i1 * g1 + e1, 0.f);
        u32 h, l;
        bsplit2(y0, y1, h, l);
        *(u32*)(sm + dHo + r0 * ldd + c * 2) = h;
        *(u32*)(sm + dLo + r0 * ldd + c * 2) = l;
        bsplit2(y2, y3, h, l);
        *(u32*)(sm + dHo + (r0 + 8) * ldd + c * 2) = h;
        *(u32*)(sm + dLo + (r0 + 8) * ldd + c * 2) = l;
    }
}

extern __shared__ char smc[];

__global__ __launch_bounds__(NTH, 1)
void sa_mma_kernel(const float* __restrict__ xyz, const float* __restrict__ feat,
                   const int* __restrict__ scanidx, const int* __restrict__ group_idx,
                   const float* __restrict__ W1, const float* __restrict__ b1,
                   const float* __restrict__ g1, const float* __restrict__ be1,
                   const float* __restrict__ W2, const float* __restrict__ b2,
                   const float* __restrict__ g2, const float* __restrict__ be2,
                   const float* __restrict__ W3, const float* __restrict__ b3,
                   const float* __restrict__ g3, const float* __restrict__ be3,
                   const float* __restrict__ Wa1, const float* __restrict__ ba1,
                   const float* __restrict__ Wa2, const float* __restrict__ ba2,
                   const float* __restrict__ Wo, const float* __restrict__ bo,
                   float* __restrict__ out_xyz, float* __restrict__ out_feat) {
    char* sm = smc;
    const u32 sb = s2u(sm);
    const int tid = threadIdx.x, lane = tid & 31, warp = tid >> 5;
    const int m0 = blockIdx.x * 2;

    // ---- zero X0 (hi+lo) ----
    for (u32 i = (u32)tid * 16u; i < 22528u; i += NTH * 16u)
        *(float4*)(sm + X0H_O + i) = make_float4(0.f, 0.f, 0.f, 0.f);
    if (tid < ROWS) ((int*)(sm + GIDX_O))[tid] = group_idx[(size_t)(m0 + (tid >> 5)) * 32 + (tid & 31)];
    __syncthreads();

    // ---- gather: rel (cols 0..2) + features (cols 3..66), split bf16 ----
    if (tid < ROWS) {
        int gi = ((int*)(sm + GIDX_O))[tid];
        int si = scanidx[m0 + (tid >> 5)];
#pragma unroll
        for (int d = 0; d < 3; d++) {
            float rv = __ldg(xyz + (size_t)gi * 3 + d) - __ldg(xyz + (size_t)si * 3 + d);
            ((float*)(sm + REL_O))[tid * 3 + d] = rv;
            __nv_bfloat16 h = __float2bfloat16(rv);
            __nv_bfloat16 l = __float2bfloat16(rv - __bfloat162float(h));
            *(__nv_bfloat16*)(sm + X0H_O + tid * LDA_X0 + d * 2) = h;
            *(__nv_bfloat16*)(sm + X0L_O + tid * LDA_X0 + d * 2) = l;
        }
    }
    {
        const float4* f4 = (const float4*)feat;
        for (int i = tid; i < ROWS * 16; i += NTH) {
            int r = i >> 4, c = i & 15;
            int gi = ((int*)(sm + GIDX_O))[r];
            float4 v = __ldg(f4 + (size_t)gi * 16 + c);
            float vv[4] = { v.x, v.y, v.z, v.w };
#pragma unroll
            for (int t = 0; t < 4; t++) {
                int col = 3 + c * 4 + t;
                __nv_bfloat16 h = __float2bfloat16(vv[t]);
                __nv_bfloat16 l = __float2bfloat16(vv[t] - __bfloat162float(h));
                *(__nv_bfloat16*)(sm + X0H_O + r * LDA_X0 + col * 2) = h;
                *(__nv_bfloat16*)(sm + X0L_O + r * LDA_X0 + col * 2) = l;
            }
        }
    }
    // (run_layer's first __syncthreads orders gather before gemm)

    // ---- L1: 67(->80) -> 128 ----
    {
        float C4[4][4];
#pragma unroll
        for (int a = 0; a < 4; a++)
#pragma unroll
            for (int e = 0; e < 4; e++) C4[a][e] = 0.f;
        run_layer<4, 7>(sm, sb, X0H_O, X0L_O, LDA_X0, W1, 67, 80, C4);
        ln_epilogue<4>(sm, C4, b1, g1, be1, H12H_O, H12L_O, LDA_H12, 1.f / 128.f);
    }
    // ---- L2: 128 -> 128 (in-place H1 -> H2) ----
    {
        float C4[4][4];
#pragma unroll
        for (int a = 0; a < 4; a++)
#pragma unroll
            for (int e = 0; e < 4; e++) C4[a][e] = 0.f;
        run_layer<4, 7>(sm, sb, H12H_O, H12L_O, LDA_H12, W2, 128, 128, C4);
        ln_epilogue<4>(sm, C4, b2, g2, be2, H12H_O, H12L_O, LDA_H12, 1.f / 128.f);
    }
    // ---- L3: 128 -> 256 ----
    float C8[8][4];
    {
#pragma unroll
        for (int a = 0; a < 8; a++)
#pragma unroll
            for (int e = 0; e < 4; e++) C8[a][e] = 0.f;
        run_layer<8, 8>(sm, sb, H12H_O, H12L_O, LDA_H12, W3, 128, 128, C8);
        ln_epilogue<8>(sm, C8, b3, g3, be3, H3H_O, H3L_O, LDA_H3, 1.f / 256.f);
    }
    // ---- attention GEMM: [h3] @ Wa1[3:259] (K=256 -> 256) ----
    {
#pragma unroll
        for (int a = 0; a < 8; a++)
#pragma unroll
            for (int e = 0; e < 4; e++) C8[a][e] = 0.f;
        run_layer<8, 8>(sm, sb, H3H_O, H3L_O, LDA_H3, Wa1 + 3 * 256, 256, 256, C8);
    }
    // ---- attention epilogue: relu(C + ba1 + rel@Wa1[0:3]) . Wa2 -> scores ----
    {
        const int rt = warp & 3, cg = warp >> 2;
        const int r0 = rt * 16 + (lane >> 2), r1 = r0 + 8;
        const int c0 = cg * 64 + (lane & 3) * 2;
        const float* rel = (const float*)(sm + REL_O);
        float a0 = rel[r0 * 3], a1 = rel[r0 * 3 + 1], a2 = rel[r0 * 3 + 2];
        float d0 = rel[r1 * 3], d1 = rel[r1 * 3 + 1], d2 = rel[r1 * 3 + 2];
        float s0 = 0.f, s1 = 0.f;
#pragma unroll
        for (int nt = 0; nt < 8; nt++) {
#pragma unroll
            for (int e = 0; e < 2; e++) {
                int c = c0 + nt * 8 + e;
                float w0 = __ldg(Wa1 + c), w1 = __ldg(Wa1 + 256 + c), w2 = __ldg(Wa1 + 512 + c);
                float bb = __ldg(ba1 + c), wa = __ldg(Wa2 + c);
                float v0 = C8[nt][e]     + bb + a0 * w0 + a1 * w1 + a2 * w2;
                float v1 = C8[nt][2 + e] + bb + d0 * w0 + d1 * w1 + d2 * w2;
                s0 += fmaxf(v0, 0.f) * wa;
                s1 += fmaxf(v1, 0.f) * wa;
            }
        }
#pragma unroll
        for (int o = 1; o <= 2; o <<= 1) {
            s0 += __shfl_xor_sync(0xffffffffu, s0, o);
            s1 += __shfl_xor_sync(0xffffffffu, s1, o);
        }
        float* scp = (float*)(sm + SCP_O);
        if ((lane & 3) == 0) { scp[r0 * 4 + cg] = s0; scp[r1 * 4 + cg] = s1; }
    }
    __syncthreads();

    // ---- softmax over K=32 (warp 0 -> query 0, warp 1 -> query 1) ----
    if (warp < 2) {
        const float* scp = (const float*)(sm + SCP_O);
        int r = warp * 32 + lane;
        float v = scp[r * 4] + scp[r * 4 + 1] + scp[r * 4 + 2] + scp[r * 4 + 3] + __ldg(ba2);
        float mx = v;
#pragma unroll
        for (int o = 16; o > 0; o >>= 1) mx = fmaxf(mx, __shfl_xor_sync(0xffffffffu, mx, o));
        float e = __expf(v - mx);
        float s = e;
#pragma unroll
        for (int o = 16; o > 0; o >>= 1) s += __shfl_xor_sync(0xffffffffu, s, o);
        ((float*)(sm + WGT_O))[r] = e / s;
    }
    __syncthreads();

    // ---- weighted sum over K (reconstruct h3 = hi + lo) ----
    {
        int c = tid & 255, q = tid >> 8;
        const float* wgt = (const float*)(sm + WGT_O);
        float a = 0.f;
#pragma unroll 8
        for (int k = 0; k < 32; k++) {
            int r = q * 32 + k;
            float h = __bfloat162float(*(__nv_bfloat16*)(sm + H3H_O + r * LDA_H3 + c * 2))
                    + __bfloat162float(*(__nv_bfloat16*)(sm + H3L_O + r * LDA_H3 + c * 2));
            a = fmaf(wgt[r], h, a);
        }
        ((float*)(sm + WSM_O))[q * 256 + c] = a;
    }
    __syncthreads();

    // ---- output projection ----
    {
        int c = tid & 255, q = tid >> 8;
        const float* ws = (const float*)(sm + WSM_O) + q * 256;
        float o = __ldg(bo + c);
#pragma unroll 4
        for (int k = 0; k < 256; k++)
            o = fmaf(ws[k], __ldg(Wo + (size_t)k * 256 + c), o);
        out_feat[(size_t)(m0 + q) * 256 + c] = o;
    }

    if (out_xyz != nullptr && tid < 6) {
        int mi = tid / 3, d = tid % 3;
        int si = scanidx[m0 + mi];
        out_xyz[(size_t)(m0 + mi) * 3 + d] = __ldg(xyz + (size_t)si * 3 + d);
    }
}

extern "C" void kernel_launch(void* const* d_in, const int* in_sizes, int n_in,
                              void* d_out, int out_size) {
    const float* xyz       = (const float*)d_in[0];
    const float* feat      = (const float*)d_in[1];
    const int*   scanidx   = (const int*)d_in[2];
    const int*   group_idx = (const int*)d_in[3];
    const float* W1  = (const float*)d_in[4];
    const float* b1  = (const float*)d_in[5];
    const float* g1  = (const float*)d_in[6];
    const float* be1 = (const float*)d_in[7];
    const float* W2  = (const float*)d_in[8];
    const float* b2  = (const float*)d_in[9];
    const float* g2  = (const float*)d_in[10];
    const float* be2 = (const float*)d_in[11];
    const float* W3  = (const float*)d_in[12];
    const float* b3  = (const float*)d_in[13];
    const float* g3  = (const float*)d_in[14];
    const float* be3 = (const float*)d_in[15];
    const float* Wa1 = (const float*)d_in[16];
    const float* ba1 = (const float*)d_in[17];
    const float* Wa2 = (const float*)d_in[18];
    const float* ba2 = (const float*)d_in[19];
    const float* Wo  = (const float*)d_in[20];
    const float* bo  = (const float*)d_in[21];

    const int M = in_sizes[2];

    float* out_xyz  = nullptr;
    float* out_feat = (float*)d_out;
    if (out_size == M * 259) {
        out_xyz  = (float*)d_out;
        out_feat = (float*)d_out + (size_t)M * 3;
    }

    cudaFuncSetAttribute(sa_mma_kernel,
                         cudaFuncAttributeMaxDynamicSharedMemorySize, (int)SMEM_SZ);

    sa_mma_kernel<<<M / 2, NTH, SMEM_SZ>>>(
        xyz, feat, scanidx, group_idx,
        W1, b1, g1, be1, W2, b2, g2, be2, W3, b3, g3, be3,
        Wa1, ba1, Wa2, ba2, Wo, bo,
        out_xyz, out_feat);
}

// round 9
// speedup vs baseline: 1.7086x; 1.2853x over previous
#include <cuda_runtime.h>
#include <cuda_bf16.h>
#include <cstdint>

// SetAbstraction fused — HMMA split-bf16 3-pass, round 9:
//  * prep kernel pre-splits weights to bf16 hi/lo in [n][k] layout (global)
//  * main kernel stages B chunks via cp.async (16B, no conversion)
//  * R=2 decomposition: warp = (rowtile warp&1: 32 rows = 2 m-tiles) x (colgroup warp>>1: N/8 cols)
//  * ldmatrix.x4 for B (two n-tiles per instruction)
// D += Ah*Bh + Al*Bh + Ah*Bl   (error ~2^-18, measured 3.1e-6)

typedef unsigned u32;

#define NTH 512
#define ROWS 64

// ---- SMEM byte offsets ----
#define X0H_O   0u          // [64][88 bf16] stride 176
#define X0L_O   11264u
#define H12H_O  22528u      // [64][136 bf16] stride 272
#define H12L_O  39936u
#define H3H_O   57344u      // [64][264 bf16] stride 528
#define H3L_O   91136u
#define BH0_O   124928u     // B chunk: [256][40 bf16] stride 80
#define BL0_O   145408u
#define BH1_O   165888u
#define BL1_O   186368u
#define RED_O   206848u     // 64*8 float2
#define SCP_O   210944u     // 64*8 float
#define WGT_O   212992u     // 64 float
#define WSM_O   213248u     // 512 float
#define REL_O   215296u     // 64*3 float
#define GIDX_O  216064u     // 64 int
#define SMEM_SZ 216320u

#define LDA_X0  176
#define LDA_H12 272
#define LDA_H3  528
#define LDB     80

// ---- prepped weights: split bf16, [n][k] layout ----
// L0: W1t  off 0      K=80  N=128 (FI=67)
// L1: W2t  off 10240  K=128 N=128
// L2: W3t  off 26624  K=128 N=256
// L3: Wa1t off 59392  K=256 N=256  (rows 3..258 of Wa1)
#define WTOT 124928
__device__ __align__(16) __nv_bfloat16 g_WH[WTOT];
__device__ __align__(16) __nv_bfloat16 g_WL[WTOT];

// chunk schedule (19 chunks)
__device__ const int CH_OFF[19] = {0,0,0, 10240,10240,10240,10240, 26624,26624,26624,26624,
                                   59392,59392,59392,59392,59392,59392,59392,59392};
__device__ const int CH_K[19]   = {80,80,80, 128,128,128,128, 128,128,128,128,
                                   256,256,256,256,256,256,256,256};
__device__ const int CH_K0[19]  = {0,32,64, 0,32,64,96, 0,32,64,96, 0,32,64,96,128,160,192,224};
__device__ const int CH_NBS[19] = {2,2,1, 2,2,2,2, 2,2,2,2, 2,2,2,2,2,2,2,2};  // log2(16B vec/row)
__device__ const int CH_N[19]   = {128,128,128, 128,128,128,128, 256,256,256,256,
                                   256,256,256,256,256,256,256,256};

__global__ void prep_kernel(const float* __restrict__ W1, const float* __restrict__ W2,
                            const float* __restrict__ W3, const float* __restrict__ Wa1) {
    int i = blockIdx.x * 256 + threadIdx.x;
    if (i >= WTOT) return;
    int off, K, N, FI; const float* W;
    if (i < 10240)      { off = 0;     K = 80;  N = 128; FI = 67;  W = W1; }
    else if (i < 26624) { off = 10240; K = 128; N = 128; FI = 128; W = W2; }
    else if (i < 59392) { off = 26624; K = 128; N = 256; FI = 128; W = W3; }
    else                { off = 59392; K = 256; N = 256; FI = 256; W = Wa1 + 3 * 256; }
    int l = i - off;
    int n = l / K, k = l % K;
    float v = (k < FI) ? W[(size_t)k * N + n] : 0.f;
    __nv_bfloat16 h = __float2bfloat16(v);
    __nv_bfloat16 lo = __float2bfloat16(v - __bfloat162float(h));
    g_WH[i] = h; g_WL[i] = lo;
}

__device__ __forceinline__ u32 s2u(const void* p) {
    u32 a; asm("{ .reg .u64 t; cvta.to.shared.u64 t, %1; cvt.u32.u64 %0, t; }" : "=r"(a) : "l"(p));
    return a;
}
__device__ __forceinline__ void cpa16s(u32 dst, const void* src) {
    asm volatile("cp.async.ca.shared.global [%0], [%1], 16;" :: "r"(dst), "l"(src));
}
#define CP_COMMIT asm volatile("cp.async.commit_group;")
#define CP_WAIT0  asm volatile("cp.async.wait_group 0;")

__device__ __forceinline__ void ldsm4(u32 a[4], u32 addr) {
    asm volatile("ldmatrix.sync.aligned.m8n8.x4.shared.b16 {%0,%1,%2,%3}, [%4];"
                 : "=r"(a[0]), "=r"(a[1]), "=r"(a[2]), "=r"(a[3]) : "r"(addr));
}
__device__ __forceinline__ void mma16816(float c[4], const u32 a[4], const u32 b[2]) {
    asm volatile("mma.sync.aligned.m16n8k16.row.col.f32.bf16.bf16.f32 "
                 "{%0,%1,%2,%3}, {%4,%5,%6,%7}, {%8,%9}, {%0,%1,%2,%3};"
                 : "+f"(c[0]), "+f"(c[1]), "+f"(c[2]), "+f"(c[3])
                 : "r"(a[0]), "r"(a[1]), "r"(a[2]), "r"(a[3]), "r"(b[0]), "r"(b[1]));
}
__device__ __forceinline__ void bsplit2(float y0, float y1, u32& hw, u32& lw) {
    __nv_bfloat16 h0 = __float2bfloat16(y0), h1 = __float2bfloat16(y1);
    __nv_bfloat16 l0 = __float2bfloat16(y0 - __bfloat162float(h0));
    __nv_bfloat16 l1 = __float2bfloat16(y1 - __bfloat162float(h1));
    __nv_bfloat162 a; a.x = h0; a.y = h1; hw = *(u32*)&a;
    __nv_bfloat162 c; c.x = l0; c.y = l1; lw = *(u32*)&c;
}

// Stage chunk ci into B buffer `buf` via cp.async.
__device__ __forceinline__ void stage_chunk(u32 sb, int buf, int ci) {
    const int off = CH_OFF[ci], K = CH_K[ci], k0 = CH_K0[ci];
    const int nbs = CH_NBS[ci], N = CH_N[ci];
    const int nb = 1 << nbs;
    const int ops = N << nbs;
    const u32 dH = sb + (buf ? BH1_O : BH0_O);
    const u32 dL = sb + (buf ? BL1_O : BL0_O);
    const __nv_bfloat16* sH = g_WH + off + k0;
    const __nv_bfloat16* sL = g_WL + off + k0;
    for (int i = threadIdx.x; i < ops; i += NTH) {
        int n = i >> nbs, v = i & (nb - 1);
        cpa16s(dH + n * LDB + v * 16, sH + n * K + v * 8);
        cpa16s(dL + n * LDB + v * 16, sL + n * K + v * 8);
    }
}

// GEMM of one staged chunk. NTN n-tiles per warp (2 or 4). R=2: 2 m-tiles.
template<int NTN>
__device__ __forceinline__ void chunk_gemm(u32 aH, u32 aL, int lda,
                                           u32 bH, u32 bL, int k0, int nk,
                                           float (&C)[2][NTN][4]) {
    const int lane = threadIdx.x & 31, warp = threadIdx.x >> 5;
    const int rt = warp & 1, cg = warp >> 1;
    constexpr int NW = NTN * 8;
    const u32 aBase = (u32)((rt * 32 + (lane & 15)) * lda + (lane >> 4) * 16);
    const u32 bBase = (u32)((cg * NW + (lane & 7) + ((lane >> 4) << 3)) * LDB
                            + ((lane >> 3) & 1) * 16);
    for (int ks = 0; ks < nk; ks++) {
        const u32 kb = (u32)((k0 + ks * 16) * 2);
        u32 ah[2][4], al[2][4];
#pragma unroll
        for (int mt = 0; mt < 2; mt++) {
            u32 ao = aBase + (u32)(mt * 16 * lda) + kb;
            ldsm4(ah[mt], aH + ao);
            ldsm4(al[mt], aL + ao);
        }
#pragma unroll
        for (int p = 0; p < NTN / 2; p++) {
            u32 bh[4], bl[4];
            u32 bo = bBase + (u32)(p * 16 * LDB) + (u32)(ks * 32);
            ldsm4(bh, bH + bo);
            ldsm4(bl, bL + bo);
#pragma unroll
            for (int mt = 0; mt < 2; mt++) {
                mma16816(C[mt][2 * p],     ah[mt], bh);
                mma16816(C[mt][2 * p],     al[mt], bh);
                mma16816(C[mt][2 * p],     ah[mt], bl);
                mma16816(C[mt][2 * p + 1], ah[mt], bh + 2);
                mma16816(C[mt][2 * p + 1], al[mt], bh + 2);
                mma16816(C[mt][2 * p + 1], ah[mt], bl + 2);
            }
        }
    }
}

// LayerNorm+ReLU epilogue -> split-bf16 dest. R=2 mapping.
template<int NTN>
__device__ __forceinline__ void ln_epilogue(char* sm, float (&C)[2][NTN][4],
                                            const float* __restrict__ b,
                                            const float* __restrict__ g,
                                            const float* __restrict__ be,
                                            u32 dHo, u32 dLo, int ldd, float invFO) {
    const int lane = threadIdx.x & 31, warp = threadIdx.x >> 5;
    const int rt = warp & 1, cg = warp >> 1;
    constexpr int NW = NTN * 8;
    const int c0 = cg * NW + (lane & 3) * 2;
    int rows[4];
#pragma unroll
    for (int mt = 0; mt < 2; mt++) {
        rows[mt * 2]     = rt * 32 + mt * 16 + (lane >> 2);
        rows[mt * 2 + 1] = rows[mt * 2] + 8;
    }
    float s[4] = {0.f, 0.f, 0.f, 0.f}, q[4] = {0.f, 0.f, 0.f, 0.f};
#pragma unroll
    for (int mt = 0; mt < 2; mt++)
#pragma unroll
        for (int nt = 0; nt < NTN; nt++) {
            int c = c0 + nt * 8;
            float b0 = __ldg(b + c), b1 = __ldg(b + c + 1);
            C[mt][nt][0] += b0; C[mt][nt][1] += b1;
            C[mt][nt][2] += b0; C[mt][nt][3] += b1;
            s[mt*2]   += C[mt][nt][0] + C[mt][nt][1];
            q[mt*2]   += C[mt][nt][0]*C[mt][nt][0] + C[mt][nt][1]*C[mt][nt][1];
            s[mt*2+1] += C[mt][nt][2] + C[mt][nt][3];
            q[mt*2+1] += C[mt][nt][2]*C[mt][nt][2] + C[mt][nt][3]*C[mt][nt][3];
        }
#pragma unroll
    for (int o = 1; o <= 2; o <<= 1)
#pragma unroll
        for (int h = 0; h < 4; h++) {
            s[h] += __shfl_xor_sync(0xffffffffu, s[h], o);
            q[h] += __shfl_xor_sync(0xffffffffu, q[h], o);
        }
    float2* red = (float2*)(sm + RED_O);
    if ((lane & 3) == 0)
#pragma unroll
        for (int h = 0; h < 4; h++) red[rows[h] * 8 + cg] = make_float2(s[h], q[h]);
    __syncthreads();
    float mean[4], inv[4];
#pragma unroll
    for (int h = 0; h < 4; h++) {
        float S = 0.f, Q = 0.f;
#pragma unroll
        for (int t = 0; t < 8; t++) { float2 p = red[rows[h] * 8 + t]; S += p.x; Q += p.y; }
        mean[h] = S * invFO;
        inv[h] = rsqrtf(fmaxf(Q * invFO - mean[h] * mean[h], 0.f) + 1e-5f);
    }
#pragma unroll
    for (int mt = 0; mt < 2; mt++)
#pragma unroll
        for (int nt = 0; nt < NTN; nt++) {
            int c = c0 + nt * 8;
            float g0 = __ldg(g + c), g1 = __ldg(g + c + 1);
            float e0 = __ldg(be + c), e1 = __ldg(be + c + 1);
#pragma unroll
            for (int h = 0; h < 2; h++) {
                int hh = mt * 2 + h;
                float y0 = fmaxf((C[mt][nt][2*h]   - mean[hh]) * inv[hh] * g0 + e0, 0.f);
                float y1 = fmaxf((C[mt][nt][2*h+1] - mean[hh]) * inv[hh] * g1 + e1, 0.f);
                u32 hw, lw; bsplit2(y0, y1, hw, lw);
                *(u32*)(sm + dHo + rows[hh] * ldd + c * 2) = hw;
                *(u32*)(sm + dLo + rows[hh] * ldd + c * 2) = lw;
            }
        }
}

extern __shared__ char smc[];

__global__ __launch_bounds__(NTH, 1)
void sa_mma_kernel(const float* __restrict__ xyz, const float* __restrict__ feat,
                   const int* __restrict__ scanidx, const int* __restrict__ group_idx,
                   const float* __restrict__ b1, const float* __restrict__ g1, const float* __restrict__ be1,
                   const float* __restrict__ b2, const float* __restrict__ g2, const float* __restrict__ be2,
                   const float* __restrict__ b3, const float* __restrict__ g3, const float* __restrict__ be3,
                   const float* __restrict__ Wa1, const float* __restrict__ ba1,
                   const float* __restrict__ Wa2, const float* __restrict__ ba2,
                   const float* __restrict__ Wo, const float* __restrict__ bo,
                   float* __restrict__ out_xyz, float* __restrict__ out_feat) {
    char* sm = smc;
    const u32 sb = s2u(sm);
    const int tid = threadIdx.x, lane = tid & 31, warp = tid >> 5;
    const int m0 = blockIdx.x * 2;

    // prefetch chunk 0 immediately
    stage_chunk(sb, 0, 0);
    CP_COMMIT;

    // ---- zero X0 hi+lo, load group indices ----
    for (u32 i = (u32)tid * 16u; i < 22528u; i += NTH * 16u)
        *(float4*)(sm + X0H_O + i) = make_float4(0.f, 0.f, 0.f, 0.f);
    if (tid < ROWS) ((int*)(sm + GIDX_O))[tid] = group_idx[(size_t)(m0 + (tid >> 5)) * 32 + (tid & 31)];
    __syncthreads();

    // ---- gather: rel + features, split bf16 ----
    if (tid < ROWS) {
        int gi = ((int*)(sm + GIDX_O))[tid];
        int si = scanidx[m0 + (tid >> 5)];
#pragma unroll
        for (int d = 0; d < 3; d++) {
            float rv = __ldg(xyz + (size_t)gi * 3 + d) - __ldg(xyz + (size_t)si * 3 + d);
            ((float*)(sm + REL_O))[tid * 3 + d] = rv;
            __nv_bfloat16 h = __float2bfloat16(rv);
            __nv_bfloat16 l = __float2bfloat16(rv - __bfloat162float(h));
            *(__nv_bfloat16*)(sm + X0H_O + tid * LDA_X0 + d * 2) = h;
            *(__nv_bfloat16*)(sm + X0L_O + tid * LDA_X0 + d * 2) = l;
        }
    }
    {
        const float4* f4 = (const float4*)feat;
        for (int i = tid; i < ROWS * 16; i += NTH) {
            int r = i >> 4, c = i & 15;
            int gi = ((int*)(sm + GIDX_O))[r];
            float4 v = __ldg(f4 + (size_t)gi * 16 + c);
            float vv[4] = { v.x, v.y, v.z, v.w };
#pragma unroll
            for (int t = 0; t < 4; t++) {
                int col = 3 + c * 4 + t;
                __nv_bfloat16 h = __float2bfloat16(vv[t]);
                __nv_bfloat16 l = __float2bfloat16(vv[t] - __bfloat162float(h));
                *(__nv_bfloat16*)(sm + X0H_O + r * LDA_X0 + col * 2) = h;
                *(__nv_bfloat16*)(sm + X0L_O + r * LDA_X0 + col * 2) = l;
            }
        }
    }

    int ci = 0;
    const u32 BH[2] = { sb + BH0_O, sb + BH1_O };
    const u32 BL[2] = { sb + BL0_O, sb + BL1_O };

    // ---- L1: X0(K=80) -> 128 ----
    {
        float C4[2][2][4] = {};
        for (int ch = 0; ch < 3; ch++, ci++) {
            CP_WAIT0; __syncthreads();
            if (ci + 1 < 19) stage_chunk(sb, (ci + 1) & 1, ci + 1);
            CP_COMMIT;
            chunk_gemm<2>(sb + X0H_O, sb + X0L_O, LDA_X0, BH[ci & 1], BL[ci & 1],
                          CH_K0[ci], (ch == 2) ? 1 : 2, C4);
        }
        ln_epilogue<2>(sm, C4, b1, g1, be1, H12H_O, H12L_O, LDA_H12, 1.f / 128.f);
    }
    // ---- L2: H1(K=128) -> 128 (in-place) ----
    {
        float C4[2][2][4] = {};
        for (int ch = 0; ch < 4; ch++, ci++) {
            CP_WAIT0; __syncthreads();
            if (ci + 1 < 19) stage_chunk(sb, (ci + 1) & 1, ci + 1);
            CP_COMMIT;
            chunk_gemm<2>(sb + H12H_O, sb + H12L_O, LDA_H12, BH[ci & 1], BL[ci & 1],
                          CH_K0[ci], 2, C4);
        }
        ln_epilogue<2>(sm, C4, b2, g2, be2, H12H_O, H12L_O, LDA_H12, 1.f / 128.f);
    }
    // ---- L3: H2(K=128) -> 256 ----
    float C8[2][4][4];
    {
#pragma unroll
        for (int a = 0; a < 2; a++)
#pragma unroll
            for (int n = 0; n < 4; n++)
#pragma unroll
                for (int e = 0; e < 4; e++) C8[a][n][e] = 0.f;
        for (int ch = 0; ch < 4; ch++, ci++) {
            CP_WAIT0; __syncthreads();
            if (ci + 1 < 19) stage_chunk(sb, (ci + 1) & 1, ci + 1);
            CP_COMMIT;
            chunk_gemm<4>(sb + H12H_O, sb + H12L_O, LDA_H12, BH[ci & 1], BL[ci & 1],
                          CH_K0[ci], 2, C8);
        }
        ln_epilogue<4>(sm, C8, b3, g3, be3, H3H_O, H3L_O, LDA_H3, 1.f / 256.f);
    }
    // ---- attention GEMM: H3(K=256) -> 256 ----
    {
#pragma unroll
        for (int a = 0; a < 2; a++)
#pragma unroll
            for (int n = 0; n < 4; n++)
#pragma unroll
                for (int e = 0; e < 4; e++) C8[a][n][e] = 0.f;
        for (int ch = 0; ch < 8; ch++, ci++) {
            CP_WAIT0; __syncthreads();
            if (ci + 1 < 19) stage_chunk(sb, (ci + 1) & 1, ci + 1);
            CP_COMMIT;
            chunk_gemm<4>(sb + H3H_O, sb + H3L_O, LDA_H3, BH[ci & 1], BL[ci & 1],
                          CH_K0[ci], 2, C8);
        }
    }
    // ---- attention epilogue: relu(C + ba1 + rel@Wa1[0:3]) . Wa2 ----
    {
        const int rt = warp & 1, cg = warp >> 1;
        const int c0 = cg * 32 + (lane & 3) * 2;
        int rows[4];
#pragma unroll
        for (int mt = 0; mt < 2; mt++) {
            rows[mt * 2]     = rt * 32 + mt * 16 + (lane >> 2);
            rows[mt * 2 + 1] = rows[mt * 2] + 8;
        }
        const float* rel = (const float*)(sm + REL_O);
        float s[4] = {0.f, 0.f, 0.f, 0.f};
#pragma unroll
        for (int mt = 0; mt < 2; mt++)
#pragma unroll
            for (int nt = 0; nt < 4; nt++)
#pragma unroll
                for (int e = 0; e < 2; e++) {
                    int c = c0 + nt * 8 + e;
                    float w0 = __ldg(Wa1 + c), w1 = __ldg(Wa1 + 256 + c), w2 = __ldg(Wa1 + 512 + c);
                    float bb = __ldg(ba1 + c), wa = __ldg(Wa2 + c);
#pragma unroll
                    for (int h = 0; h < 2; h++) {
                        int r = rows[mt * 2 + h];
                        float v = C8[mt][nt][2 * h + e] + bb
                                + rel[r*3] * w0 + rel[r*3+1] * w1 + rel[r*3+2] * w2;
                        s[mt * 2 + h] += fmaxf(v, 0.f) * wa;
                    }
                }
#pragma unroll
        for (int o = 1; o <= 2; o <<= 1)
#pragma unroll
            for (int h = 0; h < 4; h++) s[h] += __shfl_xor_sync(0xffffffffu, s[h], o);
        float* scp = (float*)(sm + SCP_O);
        if ((lane & 3) == 0)
#pragma unroll
            for (int h = 0; h < 4; h++) scp[rows[h] * 8 + cg] = s[h];
    }
    __syncthreads();

    // ---- softmax over K=32 ----
    if (warp < 2) {
        const float* scp = (const float*)(sm + SCP_O);
        int r = warp * 32 + lane;
        float v = __ldg(ba2);
#pragma unroll
        for (int t = 0; t < 8; t++) v += scp[r * 8 + t];
        float mx = v;
#pragma unroll
        for (int o = 16; o > 0; o >>= 1) mx = fmaxf(mx, __shfl_xor_sync(0xffffffffu, mx, o));
        float e = __expf(v - mx);
        float ssum = e;
#pragma unroll
        for (int o = 16; o > 0; o >>= 1) ssum += __shfl_xor_sync(0xffffffffu, ssum, o);
        ((float*)(sm + WGT_O))[r] = e / ssum;
    }
    __syncthreads();

    // ---- weighted sum over K (h3 = hi + lo) ----
    {
        int c = tid & 255, q = tid >> 8;
        const float* wgt = (const float*)(sm + WGT_O);
        float a = 0.f;
#pragma unroll 8
        for (int k = 0; k < 32; k++) {
            int r = q * 32 + k;
            float h = __bfloat162float(*(__nv_bfloat16*)(sm + H3H_O + r * LDA_H3 + c * 2))
                    + __bfloat162float(*(__nv_bfloat16*)(sm + H3L_O + r * LDA_H3 + c * 2));
            a = fmaf(wgt[r], h, a);
        }
        ((float*)(sm + WSM_O))[q * 256 + c] = a;
    }
    __syncthreads();

    // ---- output projection ----
    {
        int c = tid & 255, q = tid >> 8;
        const float* ws = (const float*)(sm + WSM_O) + q * 256;
        float o = __ldg(bo + c);
#pragma unroll 4
        for (int k = 0; k < 256; k++)
            o = fmaf(ws[k], __ldg(Wo + (size_t)k * 256 + c), o);
        out_feat[(size_t)(m0 + q) * 256 + c] = o;
    }

    if (out_xyz != nullptr && tid < 6) {
        int mi = tid / 3, d = tid % 3;
        int si = scanidx[m0 + mi];
        out_xyz[(size_t)(m0 + mi) * 3 + d] = __ldg(xyz + (size_t)si * 3 + d);
    }
}

extern "C" void kernel_launch(void* const* d_in, const int* in_sizes, int n_in,
                              void* d_out, int out_size) {
    const float* xyz       = (const float*)d_in[0];
    const float* feat      = (const float*)d_in[1];
    const int*   scanidx   = (const int*)d_in[2];
    const int*   group_idx = (const int*)d_in[3];
    const float* W1  = (const float*)d_in[4];
    const float* b1  = (const float*)d_in[5];
    const float* g1  = (const float*)d_in[6];
    const float* be1 = (const float*)d_in[7];
    const float* W2  = (const float*)d_in[8];
    const float* b2  = (const float*)d_in[9];
    const float* g2  = (const float*)d_in[10];
    const float* be2 = (const float*)d_in[11];
    const float* W3  = (const float*)d_in[12];
    const float* b3  = (const float*)d_in[13];
    const float* g3  = (const float*)d_in[14];
    const float* be3 = (const float*)d_in[15];
    const float* Wa1 = (const float*)d_in[16];
    const float* ba1 = (const float*)d_in[17];
    const float* Wa2 = (const float*)d_in[18];
    const float* ba2 = (const float*)d_in[19];
    const float* Wo  = (const float*)d_in[20];
    const float* bo  = (const float*)d_in[21];

    const int M = in_sizes[2];

    float* out_xyz  = nullptr;
    float* out_feat = (float*)d_out;
    if (out_size == M * 259) {
        out_xyz  = (float*)d_out;
        out_feat = (float*)d_out + (size_t)M * 3;
    }

    prep_kernel<<<(WTOT + 255) / 256, 256>>>(W1, W2, W3, Wa1);

    cudaFuncSetAttribute(sa_mma_kernel,
                         cudaFuncAttributeMaxDynamicSharedMemorySize, (int)SMEM_SZ);

    sa_mma_kernel<<<M / 2, NTH, SMEM_SZ>>>(
        xyz, feat, scanidx, group_idx,
        b1, g1, be1, b2, g2, be2, b3, g3, be3,
        Wa1, ba1, Wa2, ba2, Wo, bo,
        out_xyz, out_feat);
}